// round 14
// baseline (speedup 1.0000x reference)
#include <cuda_runtime.h>
#include <cuda_fp16.h>
#include <math.h>
#include <stdint.h>

// Problem constants
#define BB 4
#define HH 16
#define SS 2048
#define DD 1024
#define HD 64
#define MROWS (BB * SS)   // 8192

// ---------------------------------------------------------------------------
// Scratch (no allocations allowed -> __device__ globals)
// ---------------------------------------------------------------------------
__device__ __half g_Qh[BB * HH * SS * HD];
__device__ __half g_Kh[BB * HH * SS * HD];
__device__ __half g_Vt[BB * HH * HD * SS];   // [b,h,d,s] transposed
__device__ __half g_ctx[BB * SS * DD];
__device__ __half g_Xh[MROWS * DD];
__device__ __half g_Wh[4 * DD * DD];         // Wq|Wk|Wv|Wo packed
__device__ float  g_bias[3 * DD];            // bq|bk|bv packed

// ---------------------------------------------------------------------------
// helpers
// ---------------------------------------------------------------------------
__device__ __forceinline__ uint32_t smem_u32(const void* p) {
    uint32_t a;
    asm("{ .reg .u64 t; cvta.to.shared.u64 t, %1; cvt.u32.u64 %0, t; }"
        : "=r"(a) : "l"(p));
    return a;
}

// mma.sync m16n8k16 fp16 in, fp32 accumulate (in place on d)
__device__ __forceinline__ void mma_f16(float d[4], const uint32_t a[4],
                                        const uint32_t b[2]) {
    asm volatile(
        "mma.sync.aligned.m16n8k16.row.col.f32.f16.f16.f32 "
        "{%0,%1,%2,%3}, {%4,%5,%6,%7}, {%8,%9}, {%0,%1,%2,%3};"
        : "+f"(d[0]), "+f"(d[1]), "+f"(d[2]), "+f"(d[3])
        : "r"(a[0]), "r"(a[1]), "r"(a[2]), "r"(a[3]), "r"(b[0]), "r"(b[1]));
}

#define LDSM4(R0, R1, R2, R3, addr) \
    asm volatile("ldmatrix.sync.aligned.m8n8.x4.shared.b16 {%0,%1,%2,%3}, [%4];" \
                 : "=r"(R0), "=r"(R1), "=r"(R2), "=r"(R3) : "r"(addr))

__device__ __forceinline__ uint32_t packh2(float a, float b) {
    __half2 h = __floats2half2_rn(a, b);
    return *(uint32_t*)&h;
}

// ---------------------------------------------------------------------------
// Single conversion kernel + bias packing
// ---------------------------------------------------------------------------
#define XN4 (MROWS * DD / 4)        // 2097152
#define WN4 (DD * DD / 4)           // 262144

__global__ void cvt_all_kernel(const float* __restrict__ x,
                               const float* __restrict__ Wq,
                               const float* __restrict__ Wk,
                               const float* __restrict__ Wv,
                               const float* __restrict__ Wo,
                               __half* __restrict__ Xh,
                               __half* __restrict__ Wh)
{
    int i = blockIdx.x * blockDim.x + threadIdx.x;
    const float* src;
    __half* dst;
    int off;
    if (i < XN4) {
        src = x; dst = Xh; off = i;
    } else {
        int j = i - XN4;
        int w = j >> 18;            // / WN4
        off = j & (WN4 - 1);
        src = (w == 0) ? Wq : (w == 1) ? Wk : (w == 2) ? Wv : Wo;
        dst = Wh + (size_t)w * DD * DD;
    }
    float4 v = ((const float4*)src)[off];
    ((__half2*)dst)[2 * off]     = __floats2half2_rn(v.x, v.y);
    ((__half2*)dst)[2 * off + 1] = __floats2half2_rn(v.z, v.w);
}

__global__ void pack_bias_kernel(const float* __restrict__ bq,
                                 const float* __restrict__ bk,
                                 const float* __restrict__ bv,
                                 float* __restrict__ out)
{
    int i = blockIdx.x * blockDim.x + threadIdx.x;   // < 3072
    float v;
    if (i < 1024) v = bq[i];
    else if (i < 2048) v = bk[i - 1024];
    else v = bv[i - 2048];
    out[i] = v;
}

// ---------------------------------------------------------------------------
// RoPE on Q and K, half2-vectorized. Q gets extra 1/8 scale.
// ---------------------------------------------------------------------------
__global__ void rope2_kernel(__half* __restrict__ Qp, __half* __restrict__ Kp,
                             const float* __restrict__ cosb,
                             const float* __restrict__ sinb)
{
    int idx = blockIdx.x * blockDim.x + threadIdx.x;
    const int half_n = BB * HH * SS * 16;
    bool isK = idx >= half_n;
    if (isK) idx -= half_n;
    int i2 = (idx & 15) * 2;            // 0,2,..,30
    int bhs = idx >> 4;
    int s = bhs & (SS - 1);
    __half* p = (isK ? Kp : Qp) + (size_t)bhs * HD;
    float2 xl = __half22float2(*(__half2*)&p[i2]);
    float2 xh = __half22float2(*(__half2*)&p[i2 + 32]);
    float2 c  = *(const float2*)&cosb[s * HD + i2];
    float2 sn = *(const float2*)&sinb[s * HD + i2];
    float y0 = xl.x * c.x - xh.x * sn.x;
    float y1 = xl.y * c.y - xh.y * sn.y;
    float z0 = xh.x * c.x + xl.x * sn.x;
    float z1 = xh.y * c.y + xl.y * sn.y;
    if (!isK) { y0 *= 0.125f; y1 *= 0.125f; z0 *= 0.125f; z1 *= 0.125f; }
    *(__half2*)&p[i2]      = __floats2half2_rn(y0, y1);
    *(__half2*)&p[i2 + 32] = __floats2half2_rn(z0, z1);
}

// ===========================================================================
// Shared GEMM machinery: CTA tile 128x128, BK=32 halves, 8 warps (4m x 2n),
// warp tile 32x64. 4-stage cp.async ring. ldmatrix.x4 fragment loads.
// ===========================================================================
#define GBK 32
#define GPADH 40
#define GSTAGE_BYTES (2 * 128 * GPADH * 2)   // 20480
#define GNSTAGE 4
#define GEMM_SMEM (GNSTAGE * GSTAGE_BYTES)   // 81920

__device__ __forceinline__ void gemm_issue_loads(
    const __half* __restrict__ X, const __half* __restrict__ W,
    int m0, int n0, int tid, uint32_t stage_addr, int k0)
{
#pragma unroll
    for (int t = 0; t < 2; ++t) {
        int idx = tid + t * 256;       // 0..511
        int row = idx >> 2;
        int c = idx & 3;
        const __half* src = X + (size_t)(m0 + row) * 1024 + k0 + c * 8;
        uint32_t dst = stage_addr + row * (GPADH * 2) + c * 16;
        asm volatile("cp.async.cg.shared.global [%0], [%1], 16;"
                     :: "r"(dst), "l"(src));
    }
#pragma unroll
    for (int t = 0; t < 2; ++t) {
        int idx = tid + t * 256;
        int row = idx >> 2;
        int c = idx & 3;
        const __half* src = W + (size_t)(n0 + row) * 1024 + k0 + c * 8;
        uint32_t dst = stage_addr + 128 * (GPADH * 2) + row * (GPADH * 2) + c * 16;
        asm volatile("cp.async.cg.shared.global [%0], [%1], 16;"
                     :: "r"(dst), "l"(src));
    }
}

__device__ __forceinline__ void gemm_mainloop(
    const __half* __restrict__ X, const __half* __restrict__ W,
    uint32_t sb, int m0, int n0, int tid,
    int wm, int wn, float acc[2][8][4])
{
    const int lane = tid & 31;
    const int lt = lane >> 3;       // tile index 0..3
    const int ltr = lane & 7;       // row within tile

    const uint32_t a_off =
        ((wm * 32 + (lt & 1) * 8 + ltr) * GPADH + (lt >> 1) * 8) * 2;
    const uint32_t b_off = 128 * (GPADH * 2) +
        ((wn * 64 + (lt >> 1) * 8 + ltr) * GPADH + (lt & 1) * 8) * 2;

    gemm_issue_loads(X, W, m0, n0, tid, sb + 0 * GSTAGE_BYTES, 0);
    asm volatile("cp.async.commit_group;" ::: "memory");
    gemm_issue_loads(X, W, m0, n0, tid, sb + 1 * GSTAGE_BYTES, GBK);
    asm volatile("cp.async.commit_group;" ::: "memory");
    gemm_issue_loads(X, W, m0, n0, tid, sb + 2 * GSTAGE_BYTES, 2 * GBK);
    asm volatile("cp.async.commit_group;" ::: "memory");

    const int NK = 1024 / GBK;   // 32
    for (int s = 0; s < NK; ++s) {
        int t = s + 3;
        if (t < NK)
            gemm_issue_loads(X, W, m0, n0, tid,
                             sb + (t % GNSTAGE) * GSTAGE_BYTES, t * GBK);
        asm volatile("cp.async.commit_group;" ::: "memory");
        asm volatile("cp.async.wait_group 3;" ::: "memory");
        __syncthreads();

        const uint32_t st_b = sb + (s % GNSTAGE) * GSTAGE_BYTES;

#pragma unroll
        for (int kk = 0; kk < 2; ++kk) {     // 2 x k16
            uint32_t af[2][4];
#pragma unroll
            for (int mt = 0; mt < 2; ++mt) {
                LDSM4(af[mt][0], af[mt][1], af[mt][2], af[mt][3],
                      st_b + a_off + (mt * 16 * GPADH + kk * 16) * 2);
            }
            uint32_t bf[8][2];
#pragma unroll
            for (int p = 0; p < 4; ++p) {
                LDSM4(bf[2 * p][0], bf[2 * p][1], bf[2 * p + 1][0], bf[2 * p + 1][1],
                      st_b + b_off + (p * 16 * GPADH + kk * 16) * 2);
            }
#pragma unroll
            for (int mt = 0; mt < 2; ++mt)
#pragma unroll
                for (int nt = 0; nt < 8; ++nt)
                    mma_f16(acc[mt][nt], af[mt], bf[nt]);
        }
        __syncthreads();
    }
}

// ===========================================================================
// Fused QKV GEMM: N=3072 over packed Wq|Wk|Wv.
// ===========================================================================
__global__ __launch_bounds__(256, 2)
void gemm_qkv_kernel(const __half* __restrict__ X, const __half* __restrict__ W,
                     const float* __restrict__ bias,
                     __half* __restrict__ Qo, __half* __restrict__ Ko,
                     __half* __restrict__ Vo)
{
    extern __shared__ __align__(16) __half smem[];
    const uint32_t sb = smem_u32(smem);
    const int tid = threadIdx.x;
    const int wid = tid >> 5;
    const int lane = tid & 31;
    const int wm = wid >> 1;
    const int wn = wid & 1;
    const int m0 = blockIdx.y * 128;
    const int n0 = blockIdx.x * 128;        // [0, 3072)
    const int lr = lane >> 2;
    const int lc = lane & 3;

    float acc[2][8][4];
#pragma unroll
    for (int mt = 0; mt < 2; ++mt)
#pragma unroll
        for (int nt = 0; nt < 8; ++nt)
#pragma unroll
            for (int i = 0; i < 4; ++i) acc[mt][nt][i] = 0.0f;

    gemm_mainloop(X, W, sb, m0, n0, tid, wm, wn, acc);

    const int target = blockIdx.x >> 3;         // 0=Q, 1=K, 2=V
    const int h = ((blockIdx.x & 7) << 1) + wn; // head for this warp
    const int b = m0 >> 11;
    const int sq0 = m0 & 2047;

    if (target < 2) {
        __half* Y = (target == 0) ? Qo : Ko;
#pragma unroll
        for (int nt = 0; nt < 8; ++nt) {
            int dd = nt * 8 + 2 * lc;           // 0..63
            int ncol = n0 + wn * 64 + dd;
            float b0 = __ldg(&bias[ncol]);
            float b1 = __ldg(&bias[ncol + 1]);
#pragma unroll
            for (int mt = 0; mt < 2; ++mt) {
                int sq = sq0 + wm * 32 + mt * 16 + lr;
                int bh = b * HH + h;
                *(__half2*)&Y[((size_t)bh * SS + sq) * HD + dd] =
                    __floats2half2_rn(acc[mt][nt][0] + b0, acc[mt][nt][1] + b1);
                *(__half2*)&Y[((size_t)bh * SS + sq + 8) * HD + dd] =
                    __floats2half2_rn(acc[mt][nt][2] + b0, acc[mt][nt][3] + b1);
            }
        }
    } else {
        // V: stage transposed tile T[col][row] in smem, then coalesced store.
        __half* T = smem;                       // [128][136] halves
#pragma unroll
        for (int nt = 0; nt < 8; ++nt) {
            int col = wn * 64 + nt * 8 + 2 * lc;   // 0..127
            int ncol = n0 + col;
            float b0 = __ldg(&bias[ncol]);
            float b1 = __ldg(&bias[ncol + 1]);
#pragma unroll
            for (int mt = 0; mt < 2; ++mt) {
                int row = wm * 32 + mt * 16 + lr;
                T[col * 136 + row] = __float2half_rn(acc[mt][nt][0] + b0);
                T[(col + 1) * 136 + row] = __float2half_rn(acc[mt][nt][1] + b1);
                T[col * 136 + row + 8] = __float2half_rn(acc[mt][nt][2] + b0);
                T[(col + 1) * 136 + row + 8] = __float2half_rn(acc[mt][nt][3] + b1);
            }
        }
        __syncthreads();

#pragma unroll
        for (int t = 0; t < 8; ++t) {
            int idx = tid + t * 256;
            int drow = idx >> 4;                // 0..127
            int c8 = (idx & 15) * 8;
            int hh = ((blockIdx.x & 7) << 1) + (drow >> 6);
            int dd = drow & 63;
            uint4 v = *(const uint4*)&T[drow * 136 + c8];
            *(uint4*)&Vo[((size_t)(b * HH + hh) * HD + dd) * SS + sq0 + c8] = v;
        }
    }
}

// ===========================================================================
// O-projection GEMM (fp32 output)
// ===========================================================================
__global__ __launch_bounds__(256, 2)
void gemm_o_kernel(const __half* __restrict__ X, const __half* __restrict__ W,
                   const float* __restrict__ bias, float* __restrict__ Y)
{
    extern __shared__ __align__(16) __half smem[];
    const uint32_t sb = smem_u32(smem);
    const int tid = threadIdx.x;
    const int wid = tid >> 5;
    const int lane = tid & 31;
    const int wm = wid >> 1;
    const int wn = wid & 1;
    const int m0 = blockIdx.y * 128;
    const int n0 = blockIdx.x * 128;
    const int lr = lane >> 2;
    const int lc = lane & 3;

    float acc[2][8][4];
#pragma unroll
    for (int mt = 0; mt < 2; ++mt)
#pragma unroll
        for (int nt = 0; nt < 8; ++nt)
#pragma unroll
            for (int i = 0; i < 4; ++i) acc[mt][nt][i] = 0.0f;

    gemm_mainloop(X, W, sb, m0, n0, tid, wm, wn, acc);

#pragma unroll
    for (int nt = 0; nt < 8; ++nt) {
        int ncol = n0 + wn * 64 + nt * 8 + 2 * lc;
        float b0 = __ldg(&bias[ncol]);
        float b1 = __ldg(&bias[ncol + 1]);
#pragma unroll
        for (int mt = 0; mt < 2; ++mt) {
            int m = m0 + wm * 32 + mt * 16 + lr;
            *(float2*)&Y[(size_t)m * DD + ncol] =
                make_float2(acc[mt][nt][0] + b0, acc[mt][nt][1] + b1);
            *(float2*)&Y[(size_t)(m + 8) * DD + ncol] =
                make_float2(acc[mt][nt][2] + b0, acc[mt][nt][3] + b1);
        }
    }
}

// ===========================================================================
// Flash attention via mma.sync fp16. ldmatrix for Q/K/V; P fragments built
// DIRECTLY from softmax registers (acc layout == A-operand layout identity).
// BM=128 (8 warps x 16 rows), BN=64, HD=64. V arrives transposed [d][s].
// ===========================================================================
#define FPADH 72
#define H_KS0 0
#define H_VS0 (2 * 64 * FPADH)
#define H_QP  (4 * 64 * FPADH)
#define FLASH_SMEM ((4 * 64 * FPADH + 128 * FPADH) * 2)   // 55296 bytes

__device__ __forceinline__ void flash_load_kv(
    const __half* __restrict__ Kg, const __half* __restrict__ Vtg,
    int tid, uint32_t ks_addr, uint32_t vs_addr)
{
#pragma unroll
    for (int t = 0; t < 2; ++t) {
        int idx = tid + t * 256;
        int row = idx >> 3;
        int c = idx & 7;
        const __half* srcK = Kg + row * HD + c * 8;
        const __half* srcV = Vtg + (size_t)row * SS + c * 8;
        uint32_t dK = ks_addr + (row * FPADH + c * 8) * 2;
        uint32_t dV = vs_addr + (row * FPADH + c * 8) * 2;
        asm volatile("cp.async.cg.shared.global [%0], [%1], 16;" :: "r"(dK), "l"(srcK));
        asm volatile("cp.async.cg.shared.global [%0], [%1], 16;" :: "r"(dV), "l"(srcV));
    }
}

__global__ __launch_bounds__(256, 2)
void flash_h_kernel(const __half* __restrict__ Q, const __half* __restrict__ K,
                    const __half* __restrict__ Vt, __half* __restrict__ O)
{
    extern __shared__ __align__(16) __half sm[];
    const uint32_t sb = smem_u32(sm);

    const int tid = threadIdx.x;
    const int w = tid >> 5;
    const int lane = tid & 31;
    const int lr = lane >> 2;
    const int lc = lane & 3;
    const int lt = lane >> 3;       // ldmatrix tile index 0..3
    const int ltr = lane & 7;       // row within tile

    const int qt = (SS / 128 - 1) - blockIdx.x;
    const int h  = blockIdx.y;
    const int b  = blockIdx.z;
    const int bh = b * HH + h;

    const __half* Qg = Q + ((size_t)bh * SS + qt * 128) * HD;
    const __half* Kb = K + (size_t)bh * SS * HD;
    const __half* Vb = Vt + (size_t)bh * HD * SS;

    // ldmatrix lane byte offsets (B-layout for K/V, A-layout for Q)
    const uint32_t kv_off =
        (((lt >> 1) * 8 + ltr) * FPADH + (lt & 1) * 8) * 2;
    const uint32_t q_off =
        ((w * 16 + (lt & 1) * 8 + ltr) * FPADH + (lt >> 1) * 8) * 2;
    const uint32_t qp_base = sb + H_QP * 2;

    __half* QP = sm + H_QP;
#pragma unroll
    for (int t = 0; t < 4; ++t) {
        int idx = tid + t * 256;
        int row = idx >> 3;
        int c8 = (idx & 7) * 8;
        *(uint4*)&QP[row * FPADH + c8] = *(const uint4*)(Qg + row * HD + c8);
    }
    __syncthreads();

    // Q fragments via ldmatrix (A-layout)
    uint32_t qa[4][4];
#pragma unroll
    for (int kk = 0; kk < 4; ++kk) {
        LDSM4(qa[kk][0], qa[kk][1], qa[kk][2], qa[kk][3],
              qp_base + q_off + kk * 32);
    }

    float oacc[8][4];
#pragma unroll
    for (int nt = 0; nt < 8; ++nt)
#pragma unroll
        for (int i = 0; i < 4; ++i) oacc[nt][i] = 0.0f;
    float mA = -INFINITY, mB = -INFINITY, lA = 0.0f, lB = 0.0f;

    const int jmax = 2 * qt + 1;

    flash_load_kv(Kb, Vb, tid, sb + H_KS0 * 2, sb + H_VS0 * 2);
    asm volatile("cp.async.commit_group;" ::: "memory");

    for (int j = 0; j <= jmax; ++j) {
        __syncthreads();

        if (j + 1 <= jmax) {
            int st = (j + 1) & 1;
            flash_load_kv(Kb + (size_t)(j + 1) * 64 * HD,
                          Vb + (size_t)(j + 1) * 64, tid,
                          sb + (H_KS0 + st * 64 * FPADH) * 2,
                          sb + (H_VS0 + st * 64 * FPADH) * 2);
        }
        asm volatile("cp.async.commit_group;" ::: "memory");
        asm volatile("cp.async.wait_group 1;" ::: "memory");
        __syncthreads();

        const int st = j & 1;
        const uint32_t ksb = sb + (H_KS0 + st * 64 * FPADH) * 2;
        const uint32_t vsb = sb + (H_VS0 + st * 64 * FPADH) * 2;

        // ---- S = (Q/8) K^T via ldmatrix ----
        float sacc[8][4];
#pragma unroll
        for (int nt = 0; nt < 8; ++nt)
#pragma unroll
            for (int i = 0; i < 4; ++i) sacc[nt][i] = 0.0f;

#pragma unroll
        for (int kk = 0; kk < 4; ++kk) {
#pragma unroll
            for (int p = 0; p < 4; ++p) {
                uint32_t bf[4];
                LDSM4(bf[0], bf[1], bf[2], bf[3],
                      ksb + kv_off + (p * 16 * FPADH + kk * 16) * 2);
                mma_f16(sacc[2 * p], qa[kk], bf);
                mma_f16(sacc[2 * p + 1], qa[kk], bf + 2);
            }
        }

        if (j >= 2 * qt) {
            int rowA = qt * 128 + w * 16 + lr;
            int rowB = rowA + 8;
#pragma unroll
            for (int nt = 0; nt < 8; ++nt) {
                int c0 = j * 64 + nt * 8 + 2 * lc;
                int c1 = c0 + 1;
                if (c0 > rowA) sacc[nt][0] = -1.0e30f;
                if (c1 > rowA) sacc[nt][1] = -1.0e30f;
                if (c0 > rowB) sacc[nt][2] = -1.0e30f;
                if (c1 > rowB) sacc[nt][3] = -1.0e30f;
            }
        }

        // ---- online softmax ----
        float mxA = -INFINITY, mxB = -INFINITY;
#pragma unroll
        for (int nt = 0; nt < 8; ++nt) {
            mxA = fmaxf(mxA, fmaxf(sacc[nt][0], sacc[nt][1]));
            mxB = fmaxf(mxB, fmaxf(sacc[nt][2], sacc[nt][3]));
        }
        mxA = fmaxf(mxA, __shfl_xor_sync(0xffffffffu, mxA, 1));
        mxA = fmaxf(mxA, __shfl_xor_sync(0xffffffffu, mxA, 2));
        mxB = fmaxf(mxB, __shfl_xor_sync(0xffffffffu, mxB, 1));
        mxB = fmaxf(mxB, __shfl_xor_sync(0xffffffffu, mxB, 2));

        float mnA = fmaxf(mA, mxA);
        float mnB = fmaxf(mB, mxB);
        float corrA = __expf(mA - mnA);
        float corrB = __expf(mB - mnB);
        mA = mnA; mB = mnB;

        float rsA = 0.0f, rsB = 0.0f;
#pragma unroll
        for (int nt = 0; nt < 8; ++nt) {
            sacc[nt][0] = __expf(sacc[nt][0] - mnA);
            sacc[nt][1] = __expf(sacc[nt][1] - mnA);
            sacc[nt][2] = __expf(sacc[nt][2] - mnB);
            sacc[nt][3] = __expf(sacc[nt][3] - mnB);
            rsA += sacc[nt][0] + sacc[nt][1];
            rsB += sacc[nt][2] + sacc[nt][3];
        }
        rsA += __shfl_xor_sync(0xffffffffu, rsA, 1);
        rsA += __shfl_xor_sync(0xffffffffu, rsA, 2);
        rsB += __shfl_xor_sync(0xffffffffu, rsB, 1);
        rsB += __shfl_xor_sync(0xffffffffu, rsB, 2);
        lA = lA * corrA + rsA;
        lB = lB * corrB + rsB;

#pragma unroll
        for (int nt = 0; nt < 8; ++nt) {
            oacc[nt][0] *= corrA;
            oacc[nt][1] *= corrA;
            oacc[nt][2] *= corrB;
            oacc[nt][3] *= corrB;
        }

        // ---- O += P V: P fragments packed directly from sacc registers ----
        // A-frag for k-tile kk: a0 = S[lr][kk*16+2lc..+1]       = sacc[2kk][0,1]
        //                       a1 = S[lr+8][same]              = sacc[2kk][2,3]
        //                       a2 = S[lr][kk*16+8+2lc..+1]     = sacc[2kk+1][0,1]
        //                       a3 = S[lr+8][same]              = sacc[2kk+1][2,3]
#pragma unroll
        for (int kk = 0; kk < 4; ++kk) {
            uint32_t pa[4];
            pa[0] = packh2(sacc[2 * kk][0], sacc[2 * kk][1]);
            pa[1] = packh2(sacc[2 * kk][2], sacc[2 * kk][3]);
            pa[2] = packh2(sacc[2 * kk + 1][0], sacc[2 * kk + 1][1]);
            pa[3] = packh2(sacc[2 * kk + 1][2], sacc[2 * kk + 1][3]);
#pragma unroll
            for (int p = 0; p < 4; ++p) {
                uint32_t vf[4];
                LDSM4(vf[0], vf[1], vf[2], vf[3],
                      vsb + kv_off + (p * 16 * FPADH + kk * 16) * 2);
                mma_f16(oacc[2 * p], pa, vf);
                mma_f16(oacc[2 * p + 1], pa, vf + 2);
            }
        }
    }

    float invA = 1.0f / lA;
    float invB = 1.0f / lB;
    int rowA = qt * 128 + w * 16 + lr;
    __half* Og = O + ((size_t)b * SS) * DD + h * HD;
#pragma unroll
    for (int nt = 0; nt < 8; ++nt) {
        int d = nt * 8 + 2 * lc;
        *(__half2*)&Og[(size_t)rowA * DD + d] =
            __floats2half2_rn(oacc[nt][0] * invA, oacc[nt][1] * invA);
        *(__half2*)&Og[(size_t)(rowA + 8) * DD + d] =
            __floats2half2_rn(oacc[nt][2] * invB, oacc[nt][3] * invB);
    }
}

// ---------------------------------------------------------------------------
// kernel_launch
// Input order: x, mask, rope_cos, rope_sin, Wq, bq, Wk, bk, Wv, bv, Wo, bo
// ---------------------------------------------------------------------------
extern "C" void kernel_launch(void* const* d_in, const int* in_sizes, int n_in,
                              void* d_out, int out_size)
{
    (void)in_sizes; (void)n_in; (void)out_size;

    const float* x    = (const float*)d_in[0];
    const float* cosb = (const float*)d_in[2];
    const float* sinb = (const float*)d_in[3];
    const float* Wq = (const float*)d_in[4];
    const float* bq = (const float*)d_in[5];
    const float* Wk = (const float*)d_in[6];
    const float* bk = (const float*)d_in[7];
    const float* Wv = (const float*)d_in[8];
    const float* bv = (const float*)d_in[9];
    const float* Wo = (const float*)d_in[10];
    const float* bo = (const float*)d_in[11];
    float* out = (float*)d_out;

    __half *Qh, *Kh, *Vt, *Ch, *Xh, *Wh;
    float* biasp;
    cudaGetSymbolAddress((void**)&Qh, g_Qh);
    cudaGetSymbolAddress((void**)&Kh, g_Kh);
    cudaGetSymbolAddress((void**)&Vt, g_Vt);
    cudaGetSymbolAddress((void**)&Ch, g_ctx);
    cudaGetSymbolAddress((void**)&Xh, g_Xh);
    cudaGetSymbolAddress((void**)&Wh, g_Wh);
    cudaGetSymbolAddress((void**)&biasp, g_bias);

    cudaFuncSetAttribute(gemm_qkv_kernel,
                         cudaFuncAttributeMaxDynamicSharedMemorySize, GEMM_SMEM);
    cudaFuncSetAttribute(gemm_o_kernel,
                         cudaFuncAttributeMaxDynamicSharedMemorySize, GEMM_SMEM);
    cudaFuncSetAttribute(flash_h_kernel,
                         cudaFuncAttributeMaxDynamicSharedMemorySize, FLASH_SMEM);

    // --- convert all fp32 inputs to fp16 + pack bias ---
    int total4 = XN4 + 4 * WN4;
    cvt_all_kernel<<<total4 / 256, 256>>>(x, Wq, Wk, Wv, Wo, Xh, Wh);
    pack_bias_kernel<<<12, 256>>>(bq, bk, bv, biasp);

    // --- fused QKV projection ---
    gemm_qkv_kernel<<<dim3(24, 64), 256, GEMM_SMEM>>>(Xh, Wh, biasp, Qh, Kh, Vt);

    // --- rope on Q and K (Q gets 1/8 scale), half2-vectorized ---
    int rope_threads = 2 * BB * HH * SS * 16;
    rope2_kernel<<<rope_threads / 256, 256>>>(Qh, Kh, cosb, sinb);

    // --- attention ---
    flash_h_kernel<<<dim3(SS / 128, HH, BB), 256, FLASH_SMEM>>>(Qh, Kh, Vt, Ch);

    // --- output projection ---
    gemm_o_kernel<<<dim3(8, 64), 256, GEMM_SMEM>>>(Ch, Wh + 3 * DD * DD, bo, out);
}

// round 15
// speedup vs baseline: 1.5167x; 1.5167x over previous
#include <cuda_runtime.h>
#include <cuda_fp16.h>
#include <math.h>
#include <stdint.h>

// Problem constants
#define BB 4
#define HH 16
#define SS 2048
#define DD 1024
#define HD 64
#define MROWS (BB * SS)   // 8192

// ---------------------------------------------------------------------------
// Scratch (no allocations allowed -> __device__ globals)
// ---------------------------------------------------------------------------
__device__ __half g_Qh[BB * HH * SS * HD];
__device__ __half g_Kh[BB * HH * SS * HD];
__device__ __half g_Vt[BB * HH * HD * SS];   // [b,h,d,s] transposed
__device__ __half g_ctx[BB * SS * DD];
__device__ __half g_Xh[MROWS * DD];
__device__ __half g_Wh[4 * DD * DD];         // Wq|Wk|Wv|Wo packed
__device__ float  g_bias[3 * DD];            // bq|bk|bv packed

// ---------------------------------------------------------------------------
// helpers
// ---------------------------------------------------------------------------
__device__ __forceinline__ uint32_t smem_u32(const void* p) {
    uint32_t a;
    asm("{ .reg .u64 t; cvta.to.shared.u64 t, %1; cvt.u32.u64 %0, t; }"
        : "=r"(a) : "l"(p));
    return a;
}

// mma.sync m16n8k16 fp16 in, fp32 accumulate (in place on d)
__device__ __forceinline__ void mma_f16(float d[4], const uint32_t a[4],
                                        const uint32_t b[2]) {
    asm volatile(
        "mma.sync.aligned.m16n8k16.row.col.f32.f16.f16.f32 "
        "{%0,%1,%2,%3}, {%4,%5,%6,%7}, {%8,%9}, {%0,%1,%2,%3};"
        : "+f"(d[0]), "+f"(d[1]), "+f"(d[2]), "+f"(d[3])
        : "r"(a[0]), "r"(a[1]), "r"(a[2]), "r"(a[3]), "r"(b[0]), "r"(b[1]));
}

#define LDSM4(R0, R1, R2, R3, addr) \
    asm volatile("ldmatrix.sync.aligned.m8n8.x4.shared.b16 {%0,%1,%2,%3}, [%4];" \
                 : "=r"(R0), "=r"(R1), "=r"(R2), "=r"(R3) : "r"(addr))

// ---------------------------------------------------------------------------
// Single conversion kernel + bias packing
// ---------------------------------------------------------------------------
#define XN4 (MROWS * DD / 4)        // 2097152
#define WN4 (DD * DD / 4)           // 262144

__global__ void cvt_all_kernel(const float* __restrict__ x,
                               const float* __restrict__ Wq,
                               const float* __restrict__ Wk,
                               const float* __restrict__ Wv,
                               const float* __restrict__ Wo,
                               __half* __restrict__ Xh,
                               __half* __restrict__ Wh)
{
    int i = blockIdx.x * blockDim.x + threadIdx.x;
    const float* src;
    __half* dst;
    int off;
    if (i < XN4) {
        src = x; dst = Xh; off = i;
    } else {
        int j = i - XN4;
        int w = j >> 18;            // / WN4
        off = j & (WN4 - 1);
        src = (w == 0) ? Wq : (w == 1) ? Wk : (w == 2) ? Wv : Wo;
        dst = Wh + (size_t)w * DD * DD;
    }
    float4 v = ((const float4*)src)[off];
    ((__half2*)dst)[2 * off]     = __floats2half2_rn(v.x, v.y);
    ((__half2*)dst)[2 * off + 1] = __floats2half2_rn(v.z, v.w);
}

__global__ void pack_bias_kernel(const float* __restrict__ bq,
                                 const float* __restrict__ bk,
                                 const float* __restrict__ bv,
                                 float* __restrict__ out)
{
    int i = blockIdx.x * blockDim.x + threadIdx.x;   // < 3072
    float v;
    if (i < 1024) v = bq[i];
    else if (i < 2048) v = bk[i - 1024];
    else v = bv[i - 2048];
    out[i] = v;
}

// ---------------------------------------------------------------------------
// RoPE on Q and K, half2-vectorized. Q gets extra 1/8 scale.
// ---------------------------------------------------------------------------
__global__ void rope2_kernel(__half* __restrict__ Qp, __half* __restrict__ Kp,
                             const float* __restrict__ cosb,
                             const float* __restrict__ sinb)
{
    int idx = blockIdx.x * blockDim.x + threadIdx.x;
    const int half_n = BB * HH * SS * 16;
    bool isK = idx >= half_n;
    if (isK) idx -= half_n;
    int i2 = (idx & 15) * 2;            // 0,2,..,30
    int bhs = idx >> 4;
    int s = bhs & (SS - 1);
    __half* p = (isK ? Kp : Qp) + (size_t)bhs * HD;
    float2 xl = __half22float2(*(__half2*)&p[i2]);
    float2 xh = __half22float2(*(__half2*)&p[i2 + 32]);
    float2 c  = *(const float2*)&cosb[s * HD + i2];
    float2 sn = *(const float2*)&sinb[s * HD + i2];
    float y0 = xl.x * c.x - xh.x * sn.x;
    float y1 = xl.y * c.y - xh.y * sn.y;
    float z0 = xh.x * c.x + xl.x * sn.x;
    float z1 = xh.y * c.y + xl.y * sn.y;
    if (!isK) { y0 *= 0.125f; y1 *= 0.125f; z0 *= 0.125f; z1 *= 0.125f; }
    *(__half2*)&p[i2]      = __floats2half2_rn(y0, y1);
    *(__half2*)&p[i2 + 32] = __floats2half2_rn(z0, z1);
}

// ===========================================================================
// Shared GEMM machinery: CTA tile 128x128, BK=32 halves, 8 warps (4m x 2n),
// warp tile 32x64. 4-stage cp.async ring, single-sync stage rotation.
// ===========================================================================
#define GBK 32
#define GPADH 40
#define GSTAGE_BYTES (2 * 128 * GPADH * 2)   // 20480
#define GNSTAGE 4
#define GEMM_SMEM (GNSTAGE * GSTAGE_BYTES)   // 81920

__device__ __forceinline__ void gemm_issue_loads(
    const __half* __restrict__ X, const __half* __restrict__ W,
    int m0, int n0, int tid, uint32_t stage_addr, int k0)
{
#pragma unroll
    for (int t = 0; t < 2; ++t) {
        int idx = tid + t * 256;       // 0..511
        int row = idx >> 2;
        int c = idx & 3;
        const __half* src = X + (size_t)(m0 + row) * 1024 + k0 + c * 8;
        uint32_t dst = stage_addr + row * (GPADH * 2) + c * 16;
        asm volatile("cp.async.cg.shared.global [%0], [%1], 16;"
                     :: "r"(dst), "l"(src));
    }
#pragma unroll
    for (int t = 0; t < 2; ++t) {
        int idx = tid + t * 256;
        int row = idx >> 2;
        int c = idx & 3;
        const __half* src = W + (size_t)(n0 + row) * 1024 + k0 + c * 8;
        uint32_t dst = stage_addr + 128 * (GPADH * 2) + row * (GPADH * 2) + c * 16;
        asm volatile("cp.async.cg.shared.global [%0], [%1], 16;"
                     :: "r"(dst), "l"(src));
    }
}

__device__ __forceinline__ void gemm_mainloop(
    const __half* __restrict__ X, const __half* __restrict__ W,
    uint32_t sb, int m0, int n0, int tid,
    int wm, int wn, float acc[2][8][4])
{
    const int lane = tid & 31;
    const int lt = lane >> 3;       // tile index 0..3
    const int ltr = lane & 7;       // row within tile

    const uint32_t a_off =
        ((wm * 32 + (lt & 1) * 8 + ltr) * GPADH + (lt >> 1) * 8) * 2;
    const uint32_t b_off = 128 * (GPADH * 2) +
        ((wn * 64 + (lt >> 1) * 8 + ltr) * GPADH + (lt & 1) * 8) * 2;

    gemm_issue_loads(X, W, m0, n0, tid, sb + 0 * GSTAGE_BYTES, 0);
    asm volatile("cp.async.commit_group;" ::: "memory");
    gemm_issue_loads(X, W, m0, n0, tid, sb + 1 * GSTAGE_BYTES, GBK);
    asm volatile("cp.async.commit_group;" ::: "memory");
    gemm_issue_loads(X, W, m0, n0, tid, sb + 2 * GSTAGE_BYTES, 2 * GBK);
    asm volatile("cp.async.commit_group;" ::: "memory");

    const int NK = 1024 / GBK;   // 32
    for (int s = 0; s < NK; ++s) {
        // stage s resident when at most 2 younger groups are pending
        asm volatile("cp.async.wait_group 2;" ::: "memory");
        __syncthreads();   // also proves all threads completed compute of s-1

        // safe to overwrite slot (s+3)%4 (held stage s-1)
        int t = s + 3;
        if (t < NK) {
            gemm_issue_loads(X, W, m0, n0, tid,
                             sb + (t % GNSTAGE) * GSTAGE_BYTES, t * GBK);
            asm volatile("cp.async.commit_group;" ::: "memory");
        }

        const uint32_t st_b = sb + (s % GNSTAGE) * GSTAGE_BYTES;

#pragma unroll
        for (int kk = 0; kk < 2; ++kk) {     // 2 x k16
            uint32_t af[2][4];
#pragma unroll
            for (int mt = 0; mt < 2; ++mt) {
                LDSM4(af[mt][0], af[mt][1], af[mt][2], af[mt][3],
                      st_b + a_off + (mt * 16 * GPADH + kk * 16) * 2);
            }
            uint32_t bf[8][2];
#pragma unroll
            for (int p = 0; p < 4; ++p) {
                LDSM4(bf[2 * p][0], bf[2 * p][1], bf[2 * p + 1][0], bf[2 * p + 1][1],
                      st_b + b_off + (p * 16 * GPADH + kk * 16) * 2);
            }
#pragma unroll
            for (int mt = 0; mt < 2; ++mt)
#pragma unroll
                for (int nt = 0; nt < 8; ++nt)
                    mma_f16(acc[mt][nt], af[mt], bf[nt]);
        }
    }
    __syncthreads();   // epilogue may reuse smem
}

// ===========================================================================
// Fused QKV GEMM: N=3072 over packed Wq|Wk|Wv.
// ===========================================================================
__global__ __launch_bounds__(256, 2)
void gemm_qkv_kernel(const __half* __restrict__ X, const __half* __restrict__ W,
                     const float* __restrict__ bias,
                     __half* __restrict__ Qo, __half* __restrict__ Ko,
                     __half* __restrict__ Vo)
{
    extern __shared__ __align__(16) __half smem[];
    const uint32_t sb = smem_u32(smem);
    const int tid = threadIdx.x;
    const int wid = tid >> 5;
    const int lane = tid & 31;
    const int wm = wid >> 1;
    const int wn = wid & 1;
    const int m0 = blockIdx.y * 128;
    const int n0 = blockIdx.x * 128;        // [0, 3072)
    const int lr = lane >> 2;
    const int lc = lane & 3;

    float acc[2][8][4];
#pragma unroll
    for (int mt = 0; mt < 2; ++mt)
#pragma unroll
        for (int nt = 0; nt < 8; ++nt)
#pragma unroll
            for (int i = 0; i < 4; ++i) acc[mt][nt][i] = 0.0f;

    gemm_mainloop(X, W, sb, m0, n0, tid, wm, wn, acc);

    const int target = blockIdx.x >> 3;         // 0=Q, 1=K, 2=V
    const int h = ((blockIdx.x & 7) << 1) + wn; // head for this warp
    const int b = m0 >> 11;
    const int sq0 = m0 & 2047;

    if (target < 2) {
        __half* Y = (target == 0) ? Qo : Ko;
#pragma unroll
        for (int nt = 0; nt < 8; ++nt) {
            int dd = nt * 8 + 2 * lc;           // 0..63
            int ncol = n0 + wn * 64 + dd;
            float b0 = __ldg(&bias[ncol]);
            float b1 = __ldg(&bias[ncol + 1]);
#pragma unroll
            for (int mt = 0; mt < 2; ++mt) {
                int sq = sq0 + wm * 32 + mt * 16 + lr;
                int bh = b * HH + h;
                *(__half2*)&Y[((size_t)bh * SS + sq) * HD + dd] =
                    __floats2half2_rn(acc[mt][nt][0] + b0, acc[mt][nt][1] + b1);
                *(__half2*)&Y[((size_t)bh * SS + sq + 8) * HD + dd] =
                    __floats2half2_rn(acc[mt][nt][2] + b0, acc[mt][nt][3] + b1);
            }
        }
    } else {
        // V: stage transposed tile T[col][row] in smem, then coalesced store.
        __half* T = smem;                       // [128][136] halves
#pragma unroll
        for (int nt = 0; nt < 8; ++nt) {
            int col = wn * 64 + nt * 8 + 2 * lc;   // 0..127
            int ncol = n0 + col;
            float b0 = __ldg(&bias[ncol]);
            float b1 = __ldg(&bias[ncol + 1]);
#pragma unroll
            for (int mt = 0; mt < 2; ++mt) {
                int row = wm * 32 + mt * 16 + lr;
                T[col * 136 + row] = __float2half_rn(acc[mt][nt][0] + b0);
                T[(col + 1) * 136 + row] = __float2half_rn(acc[mt][nt][1] + b1);
                T[col * 136 + row + 8] = __float2half_rn(acc[mt][nt][2] + b0);
                T[(col + 1) * 136 + row + 8] = __float2half_rn(acc[mt][nt][3] + b1);
            }
        }
        __syncthreads();

#pragma unroll
        for (int t = 0; t < 8; ++t) {
            int idx = tid + t * 256;
            int drow = idx >> 4;                // 0..127
            int c8 = (idx & 15) * 8;
            int hh = ((blockIdx.x & 7) << 1) + (drow >> 6);
            int dd = drow & 63;
            uint4 v = *(const uint4*)&T[drow * 136 + c8];
            *(uint4*)&Vo[((size_t)(b * HH + hh) * HD + dd) * SS + sq0 + c8] = v;
        }
    }
}

// ===========================================================================
// O-projection GEMM (fp32 output)
// ===========================================================================
__global__ __launch_bounds__(256, 2)
void gemm_o_kernel(const __half* __restrict__ X, const __half* __restrict__ W,
                   const float* __restrict__ bias, float* __restrict__ Y)
{
    extern __shared__ __align__(16) __half smem[];
    const uint32_t sb = smem_u32(smem);
    const int tid = threadIdx.x;
    const int wid = tid >> 5;
    const int lane = tid & 31;
    const int wm = wid >> 1;
    const int wn = wid & 1;
    const int m0 = blockIdx.y * 128;
    const int n0 = blockIdx.x * 128;
    const int lr = lane >> 2;
    const int lc = lane & 3;

    float acc[2][8][4];
#pragma unroll
    for (int mt = 0; mt < 2; ++mt)
#pragma unroll
        for (int nt = 0; nt < 8; ++nt)
#pragma unroll
            for (int i = 0; i < 4; ++i) acc[mt][nt][i] = 0.0f;

    gemm_mainloop(X, W, sb, m0, n0, tid, wm, wn, acc);

#pragma unroll
    for (int nt = 0; nt < 8; ++nt) {
        int ncol = n0 + wn * 64 + nt * 8 + 2 * lc;
        float b0 = __ldg(&bias[ncol]);
        float b1 = __ldg(&bias[ncol + 1]);
#pragma unroll
        for (int mt = 0; mt < 2; ++mt) {
            int m = m0 + wm * 32 + mt * 16 + lr;
            *(float2*)&Y[(size_t)m * DD + ncol] =
                make_float2(acc[mt][nt][0] + b0, acc[mt][nt][1] + b1);
            *(float2*)&Y[(size_t)(m + 8) * DD + ncol] =
                make_float2(acc[mt][nt][2] + b0, acc[mt][nt][3] + b1);
        }
    }
}

// ===========================================================================
// Flash attention via mma.sync fp16 (R13 structure: P staged through smem).
// ldmatrix for Q/K/V/P. BM=128, BN=64, HD=64. V transposed [d][s].
// Single-sync stage rotation in the KV pipeline.
// ===========================================================================
#define FPADH 72
#define H_KS0 0
#define H_VS0 (2 * 64 * FPADH)
#define H_QP  (4 * 64 * FPADH)
#define FLASH_SMEM ((4 * 64 * FPADH + 128 * FPADH) * 2)   // 55296 bytes

__device__ __forceinline__ void flash_load_kv(
    const __half* __restrict__ Kg, const __half* __restrict__ Vtg,
    int tid, uint32_t ks_addr, uint32_t vs_addr)
{
#pragma unroll
    for (int t = 0; t < 2; ++t) {
        int idx = tid + t * 256;
        int row = idx >> 3;
        int c = idx & 7;
        const __half* srcK = Kg + row * HD + c * 8;
        const __half* srcV = Vtg + (size_t)row * SS + c * 8;
        uint32_t dK = ks_addr + (row * FPADH + c * 8) * 2;
        uint32_t dV = vs_addr + (row * FPADH + c * 8) * 2;
        asm volatile("cp.async.cg.shared.global [%0], [%1], 16;" :: "r"(dK), "l"(srcK));
        asm volatile("cp.async.cg.shared.global [%0], [%1], 16;" :: "r"(dV), "l"(srcV));
    }
}

__global__ __launch_bounds__(256, 2)
void flash_h_kernel(const __half* __restrict__ Q, const __half* __restrict__ K,
                    const __half* __restrict__ Vt, __half* __restrict__ O)
{
    extern __shared__ __align__(16) __half sm[];
    const uint32_t sb = smem_u32(sm);

    const int tid = threadIdx.x;
    const int w = tid >> 5;
    const int lane = tid & 31;
    const int lr = lane >> 2;
    const int lc = lane & 3;
    const int lt = lane >> 3;       // ldmatrix tile index 0..3
    const int ltr = lane & 7;       // row within tile

    const int qt = (SS / 128 - 1) - blockIdx.x;
    const int h  = blockIdx.y;
    const int b  = blockIdx.z;
    const int bh = b * HH + h;

    const __half* Qg = Q + ((size_t)bh * SS + qt * 128) * HD;
    const __half* Kb = K + (size_t)bh * SS * HD;
    const __half* Vb = Vt + (size_t)bh * HD * SS;

    // ldmatrix lane byte offsets (B-layout for K/V, A-layout for Q/P)
    const uint32_t kv_off =
        (((lt >> 1) * 8 + ltr) * FPADH + (lt & 1) * 8) * 2;
    const uint32_t p_off =
        ((w * 16 + (lt & 1) * 8 + ltr) * FPADH + (lt >> 1) * 8) * 2;
    const uint32_t qp_base = sb + H_QP * 2;

    __half* QP = sm + H_QP;
#pragma unroll
    for (int t = 0; t < 4; ++t) {
        int idx = tid + t * 256;
        int row = idx >> 3;
        int c8 = (idx & 7) * 8;
        *(uint4*)&QP[row * FPADH + c8] = *(const uint4*)(Qg + row * HD + c8);
    }
    __syncthreads();

    // Q fragments via ldmatrix (A-layout)
    uint32_t qa[4][4];
#pragma unroll
    for (int kk = 0; kk < 4; ++kk) {
        LDSM4(qa[kk][0], qa[kk][1], qa[kk][2], qa[kk][3],
              qp_base + p_off + kk * 32);
    }

    float oacc[8][4];
#pragma unroll
    for (int nt = 0; nt < 8; ++nt)
#pragma unroll
        for (int i = 0; i < 4; ++i) oacc[nt][i] = 0.0f;
    float mA = -INFINITY, mB = -INFINITY, lA = 0.0f, lB = 0.0f;

    const int jmax = 2 * qt + 1;

    flash_load_kv(Kb, Vb, tid, sb + H_KS0 * 2, sb + H_VS0 * 2);
    asm volatile("cp.async.commit_group;" ::: "memory");

    __half* Pt = QP;

    for (int j = 0; j <= jmax; ++j) {
        // stage j resident when no younger groups pending
        asm volatile("cp.async.wait_group 0;" ::: "memory");
        __syncthreads();   // also proves all threads done with stage j-1 + Pt

        if (j + 1 <= jmax) {
            int st = (j + 1) & 1;
            flash_load_kv(Kb + (size_t)(j + 1) * 64 * HD,
                          Vb + (size_t)(j + 1) * 64, tid,
                          sb + (H_KS0 + st * 64 * FPADH) * 2,
                          sb + (H_VS0 + st * 64 * FPADH) * 2);
            asm volatile("cp.async.commit_group;" ::: "memory");
        }

        const int st = j & 1;
        const uint32_t ksb = sb + (H_KS0 + st * 64 * FPADH) * 2;
        const uint32_t vsb = sb + (H_VS0 + st * 64 * FPADH) * 2;

        // ---- S = (Q/8) K^T via ldmatrix ----
        float sacc[8][4];
#pragma unroll
        for (int nt = 0; nt < 8; ++nt)
#pragma unroll
            for (int i = 0; i < 4; ++i) sacc[nt][i] = 0.0f;

#pragma unroll
        for (int kk = 0; kk < 4; ++kk) {
#pragma unroll
            for (int p = 0; p < 4; ++p) {
                uint32_t bf[4];
                LDSM4(bf[0], bf[1], bf[2], bf[3],
                      ksb + kv_off + (p * 16 * FPADH + kk * 16) * 2);
                mma_f16(sacc[2 * p], qa[kk], bf);
                mma_f16(sacc[2 * p + 1], qa[kk], bf + 2);
            }
        }

        if (j >= 2 * qt) {
            int rowA = qt * 128 + w * 16 + lr;
            int rowB = rowA + 8;
#pragma unroll
            for (int nt = 0; nt < 8; ++nt) {
                int c0 = j * 64 + nt * 8 + 2 * lc;
                int c1 = c0 + 1;
                if (c0 > rowA) sacc[nt][0] = -1.0e30f;
                if (c1 > rowA) sacc[nt][1] = -1.0e30f;
                if (c0 > rowB) sacc[nt][2] = -1.0e30f;
                if (c1 > rowB) sacc[nt][3] = -1.0e30f;
            }
        }

        // ---- online softmax ----
        float mxA = -INFINITY, mxB = -INFINITY;
#pragma unroll
        for (int nt = 0; nt < 8; ++nt) {
            mxA = fmaxf(mxA, fmaxf(sacc[nt][0], sacc[nt][1]));
            mxB = fmaxf(mxB, fmaxf(sacc[nt][2], sacc[nt][3]));
        }
        mxA = fmaxf(mxA, __shfl_xor_sync(0xffffffffu, mxA, 1));
        mxA = fmaxf(mxA, __shfl_xor_sync(0xffffffffu, mxA, 2));
        mxB = fmaxf(mxB, __shfl_xor_sync(0xffffffffu, mxB, 1));
        mxB = fmaxf(mxB, __shfl_xor_sync(0xffffffffu, mxB, 2));

        float mnA = fmaxf(mA, mxA);
        float mnB = fmaxf(mB, mxB);
        float corrA = __expf(mA - mnA);
        float corrB = __expf(mB - mnB);
        mA = mnA; mB = mnB;

        float rsA = 0.0f, rsB = 0.0f;
#pragma unroll
        for (int nt = 0; nt < 8; ++nt) {
            sacc[nt][0] = __expf(sacc[nt][0] - mnA);
            sacc[nt][1] = __expf(sacc[nt][1] - mnA);
            sacc[nt][2] = __expf(sacc[nt][2] - mnB);
            sacc[nt][3] = __expf(sacc[nt][3] - mnB);
            rsA += sacc[nt][0] + sacc[nt][1];
            rsB += sacc[nt][2] + sacc[nt][3];
        }
        rsA += __shfl_xor_sync(0xffffffffu, rsA, 1);
        rsA += __shfl_xor_sync(0xffffffffu, rsA, 2);
        rsB += __shfl_xor_sync(0xffffffffu, rsB, 1);
        rsB += __shfl_xor_sync(0xffffffffu, rsB, 2);
        lA = lA * corrA + rsA;
        lB = lB * corrB + rsB;

#pragma unroll
        for (int nt = 0; nt < 8; ++nt) {
            oacc[nt][0] *= corrA;
            oacc[nt][1] *= corrA;
            oacc[nt][2] *= corrB;
            oacc[nt][3] *= corrB;
        }

        // ---- stage P (half2) into warp-private smem rows ----
        {
            int rA = w * 16 + lr;
#pragma unroll
            for (int nt = 0; nt < 8; ++nt) {
                int c = nt * 8 + 2 * lc;
                *(__half2*)&Pt[rA * FPADH + c] =
                    __floats2half2_rn(sacc[nt][0], sacc[nt][1]);
                *(__half2*)&Pt[(rA + 8) * FPADH + c] =
                    __floats2half2_rn(sacc[nt][2], sacc[nt][3]);
            }
        }
        __syncwarp();

        // ---- O += P V via ldmatrix (P: A-layout, V: B-layout) ----
#pragma unroll
        for (int kk = 0; kk < 4; ++kk) {
            uint32_t pa[4];
            LDSM4(pa[0], pa[1], pa[2], pa[3], qp_base + p_off + kk * 32);
#pragma unroll
            for (int p = 0; p < 4; ++p) {
                uint32_t vf[4];
                LDSM4(vf[0], vf[1], vf[2], vf[3],
                      vsb + kv_off + (p * 16 * FPADH + kk * 16) * 2);
                mma_f16(oacc[2 * p], pa, vf);
                mma_f16(oacc[2 * p + 1], pa, vf + 2);
            }
        }
        __syncwarp();
    }

    float invA = 1.0f / lA;
    float invB = 1.0f / lB;
    int rowA = qt * 128 + w * 16 + lr;
    __half* Og = O + ((size_t)b * SS) * DD + h * HD;
#pragma unroll
    for (int nt = 0; nt < 8; ++nt) {
        int d = nt * 8 + 2 * lc;
        *(__half2*)&Og[(size_t)rowA * DD + d] =
            __floats2half2_rn(oacc[nt][0] * invA, oacc[nt][1] * invA);
        *(__half2*)&Og[(size_t)(rowA + 8) * DD + d] =
            __floats2half2_rn(oacc[nt][2] * invB, oacc[nt][3] * invB);
    }
}

// ---------------------------------------------------------------------------
// kernel_launch
// Input order: x, mask, rope_cos, rope_sin, Wq, bq, Wk, bk, Wv, bv, Wo, bo
// ---------------------------------------------------------------------------
extern "C" void kernel_launch(void* const* d_in, const int* in_sizes, int n_in,
                              void* d_out, int out_size)
{
    (void)in_sizes; (void)n_in; (void)out_size;

    const float* x    = (const float*)d_in[0];
    const float* cosb = (const float*)d_in[2];
    const float* sinb = (const float*)d_in[3];
    const float* Wq = (const float*)d_in[4];
    const float* bq = (const float*)d_in[5];
    const float* Wk = (const float*)d_in[6];
    const float* bk = (const float*)d_in[7];
    const float* Wv = (const float*)d_in[8];
    const float* bv = (const float*)d_in[9];
    const float* Wo = (const float*)d_in[10];
    const float* bo = (const float*)d_in[11];
    float* out = (float*)d_out;

    __half *Qh, *Kh, *Vt, *Ch, *Xh, *Wh;
    float* biasp;
    cudaGetSymbolAddress((void**)&Qh, g_Qh);
    cudaGetSymbolAddress((void**)&Kh, g_Kh);
    cudaGetSymbolAddress((void**)&Vt, g_Vt);
    cudaGetSymbolAddress((void**)&Ch, g_ctx);
    cudaGetSymbolAddress((void**)&Xh, g_Xh);
    cudaGetSymbolAddress((void**)&Wh, g_Wh);
    cudaGetSymbolAddress((void**)&biasp, g_bias);

    cudaFuncSetAttribute(gemm_qkv_kernel,
                         cudaFuncAttributeMaxDynamicSharedMemorySize, GEMM_SMEM);
    cudaFuncSetAttribute(gemm_o_kernel,
                         cudaFuncAttributeMaxDynamicSharedMemorySize, GEMM_SMEM);
    cudaFuncSetAttribute(flash_h_kernel,
                         cudaFuncAttributeMaxDynamicSharedMemorySize, FLASH_SMEM);

    // --- convert all fp32 inputs to fp16 + pack bias ---
    int total4 = XN4 + 4 * WN4;
    cvt_all_kernel<<<total4 / 256, 256>>>(x, Wq, Wk, Wv, Wo, Xh, Wh);
    pack_bias_kernel<<<12, 256>>>(bq, bk, bv, biasp);

    // --- fused QKV projection ---
    gemm_qkv_kernel<<<dim3(24, 64), 256, GEMM_SMEM>>>(Xh, Wh, biasp, Qh, Kh, Vt);

    // --- rope on Q and K (Q gets 1/8 scale), half2-vectorized ---
    int rope_threads = 2 * BB * HH * SS * 16;
    rope2_kernel<<<rope_threads / 256, 256>>>(Qh, Kh, cosb, sinb);

    // --- attention ---
    flash_h_kernel<<<dim3(SS / 128, HH, BB), 256, FLASH_SMEM>>>(Qh, Kh, Vt, Ch);

    // --- output projection ---
    gemm_o_kernel<<<dim3(8, 64), 256, GEMM_SMEM>>>(Ch, Wh + 3 * DD * DD, bo, out);
}

// round 16
// speedup vs baseline: 1.5820x; 1.0431x over previous
#include <cuda_runtime.h>
#include <cuda_fp16.h>
#include <math.h>
#include <stdint.h>

// Problem constants
#define BB 4
#define HH 16
#define SS 2048
#define DD 1024
#define HD 64
#define MROWS (BB * SS)   // 8192

// ---------------------------------------------------------------------------
// Scratch (no allocations allowed -> __device__ globals)
// ---------------------------------------------------------------------------
__device__ __half g_Qh[BB * HH * SS * HD];
__device__ __half g_Kh[BB * HH * SS * HD];
__device__ __half g_Vt[BB * HH * HD * SS];   // [b,h,d,s] transposed
__device__ __half g_ctx[BB * SS * DD];
__device__ __half g_Xh[MROWS * DD];
__device__ __half g_Wh[4 * DD * DD];         // Wq|Wk|Wv|Wo packed
__device__ float  g_bias[3 * DD];            // bq|bk|bv packed

// ---------------------------------------------------------------------------
// helpers
// ---------------------------------------------------------------------------
__device__ __forceinline__ uint32_t smem_u32(const void* p) {
    uint32_t a;
    asm("{ .reg .u64 t; cvta.to.shared.u64 t, %1; cvt.u32.u64 %0, t; }"
        : "=r"(a) : "l"(p));
    return a;
}

// mma.sync m16n8k16 fp16 in, fp32 accumulate (in place on d)
__device__ __forceinline__ void mma_f16(float d[4], const uint32_t a[4],
                                        const uint32_t b[2]) {
    asm volatile(
        "mma.sync.aligned.m16n8k16.row.col.f32.f16.f16.f32 "
        "{%0,%1,%2,%3}, {%4,%5,%6,%7}, {%8,%9}, {%0,%1,%2,%3};"
        : "+f"(d[0]), "+f"(d[1]), "+f"(d[2]), "+f"(d[3])
        : "r"(a[0]), "r"(a[1]), "r"(a[2]), "r"(a[3]), "r"(b[0]), "r"(b[1]));
}

#define LDSM4(R0, R1, R2, R3, addr) \
    asm volatile("ldmatrix.sync.aligned.m8n8.x4.shared.b16 {%0,%1,%2,%3}, [%4];" \
                 : "=r"(R0), "=r"(R1), "=r"(R2), "=r"(R3) : "r"(addr))

// ---------------------------------------------------------------------------
// Single conversion kernel (x, 4 weights, packed bias) in one launch.
// ---------------------------------------------------------------------------
#define XN4 (MROWS * DD / 4)        // 2097152
#define WN4 (DD * DD / 4)           // 262144
#define CVT_TOTAL (XN4 + 4 * WN4 + 3 * DD)

__global__ void cvt_all_kernel(const float* __restrict__ x,
                               const float* __restrict__ Wq,
                               const float* __restrict__ Wk,
                               const float* __restrict__ Wv,
                               const float* __restrict__ Wo,
                               const float* __restrict__ bq,
                               const float* __restrict__ bk,
                               const float* __restrict__ bv,
                               __half* __restrict__ Xh,
                               __half* __restrict__ Wh,
                               float* __restrict__ biasp)
{
    int i = blockIdx.x * blockDim.x + threadIdx.x;
    if (i >= CVT_TOTAL) return;
    if (i >= XN4 + 4 * WN4) {
        int j = i - (XN4 + 4 * WN4);        // < 3072
        float v;
        if (j < 1024) v = bq[j];
        else if (j < 2048) v = bk[j - 1024];
        else v = bv[j - 2048];
        biasp[j] = v;
        return;
    }
    const float* src;
    __half* dst;
    int off;
    if (i < XN4) {
        src = x; dst = Xh; off = i;
    } else {
        int j = i - XN4;
        int w = j >> 18;            // / WN4
        off = j & (WN4 - 1);
        src = (w == 0) ? Wq : (w == 1) ? Wk : (w == 2) ? Wv : Wo;
        dst = Wh + (size_t)w * DD * DD;
    }
    float4 v = ((const float4*)src)[off];
    ((__half2*)dst)[2 * off]     = __floats2half2_rn(v.x, v.y);
    ((__half2*)dst)[2 * off + 1] = __floats2half2_rn(v.z, v.w);
}

// ===========================================================================
// Shared GEMM machinery: CTA tile 128x128, BK=32 halves, 8 warps (4m x 2n),
// warp tile 32x64. 4-stage cp.async ring, single-sync stage rotation.
// ===========================================================================
#define GBK 32
#define GPADH 40
#define GSTAGE_BYTES (2 * 128 * GPADH * 2)   // 20480
#define GNSTAGE 4
#define GEMM_SMEM (GNSTAGE * GSTAGE_BYTES)   // 81920

__device__ __forceinline__ void gemm_issue_loads(
    const __half* __restrict__ X, const __half* __restrict__ W,
    int m0, int n0, int tid, uint32_t stage_addr, int k0)
{
#pragma unroll
    for (int t = 0; t < 2; ++t) {
        int idx = tid + t * 256;       // 0..511
        int row = idx >> 2;
        int c = idx & 3;
        const __half* src = X + (size_t)(m0 + row) * 1024 + k0 + c * 8;
        uint32_t dst = stage_addr + row * (GPADH * 2) + c * 16;
        asm volatile("cp.async.cg.shared.global [%0], [%1], 16;"
                     :: "r"(dst), "l"(src));
    }
#pragma unroll
    for (int t = 0; t < 2; ++t) {
        int idx = tid + t * 256;
        int row = idx >> 2;
        int c = idx & 3;
        const __half* src = W + (size_t)(n0 + row) * 1024 + k0 + c * 8;
        uint32_t dst = stage_addr + 128 * (GPADH * 2) + row * (GPADH * 2) + c * 16;
        asm volatile("cp.async.cg.shared.global [%0], [%1], 16;"
                     :: "r"(dst), "l"(src));
    }
}

__device__ __forceinline__ void gemm_mainloop(
    const __half* __restrict__ X, const __half* __restrict__ W,
    uint32_t sb, int m0, int n0, int tid,
    int wm, int wn, float acc[2][8][4])
{
    const int lane = tid & 31;
    const int lt = lane >> 3;       // tile index 0..3
    const int ltr = lane & 7;       // row within tile

    const uint32_t a_off =
        ((wm * 32 + (lt & 1) * 8 + ltr) * GPADH + (lt >> 1) * 8) * 2;
    const uint32_t b_off = 128 * (GPADH * 2) +
        ((wn * 64 + (lt >> 1) * 8 + ltr) * GPADH + (lt & 1) * 8) * 2;

    gemm_issue_loads(X, W, m0, n0, tid, sb + 0 * GSTAGE_BYTES, 0);
    asm volatile("cp.async.commit_group;" ::: "memory");
    gemm_issue_loads(X, W, m0, n0, tid, sb + 1 * GSTAGE_BYTES, GBK);
    asm volatile("cp.async.commit_group;" ::: "memory");
    gemm_issue_loads(X, W, m0, n0, tid, sb + 2 * GSTAGE_BYTES, 2 * GBK);
    asm volatile("cp.async.commit_group;" ::: "memory");

    const int NK = 1024 / GBK;   // 32
    for (int s = 0; s < NK; ++s) {
        asm volatile("cp.async.wait_group 2;" ::: "memory");
        __syncthreads();   // also proves all threads completed compute of s-1

        int t = s + 3;
        if (t < NK) {
            gemm_issue_loads(X, W, m0, n0, tid,
                             sb + (t % GNSTAGE) * GSTAGE_BYTES, t * GBK);
            asm volatile("cp.async.commit_group;" ::: "memory");
        }

        const uint32_t st_b = sb + (s % GNSTAGE) * GSTAGE_BYTES;

#pragma unroll
        for (int kk = 0; kk < 2; ++kk) {     // 2 x k16
            uint32_t af[2][4];
#pragma unroll
            for (int mt = 0; mt < 2; ++mt) {
                LDSM4(af[mt][0], af[mt][1], af[mt][2], af[mt][3],
                      st_b + a_off + (mt * 16 * GPADH + kk * 16) * 2);
            }
            uint32_t bf[8][2];
#pragma unroll
            for (int p = 0; p < 4; ++p) {
                LDSM4(bf[2 * p][0], bf[2 * p][1], bf[2 * p + 1][0], bf[2 * p + 1][1],
                      st_b + b_off + (p * 16 * GPADH + kk * 16) * 2);
            }
#pragma unroll
            for (int mt = 0; mt < 2; ++mt)
#pragma unroll
                for (int nt = 0; nt < 8; ++nt)
                    mma_f16(acc[mt][nt], af[mt], bf[nt]);
        }
    }
    __syncthreads();   // epilogue may reuse smem
}

// ===========================================================================
// Fused QKV GEMM: N=3072 over packed Wq|Wk|Wv.
// Q/K epilogue: stage half(acc+bias) in smem (acc dies), reload + fp32 rope
// (bit-identical to the former separate rope kernel), store [B,H,S,hd].
// V epilogue: smem transpose -> coalesced [B,H,hd,S] stores.
// ===========================================================================
__global__ __launch_bounds__(256, 2)
void gemm_qkv_kernel(const __half* __restrict__ X, const __half* __restrict__ W,
                     const float* __restrict__ bias,
                     const float* __restrict__ cosb,
                     const float* __restrict__ sinb,
                     __half* __restrict__ Qo, __half* __restrict__ Ko,
                     __half* __restrict__ Vo)
{
    extern __shared__ __align__(16) __half smem[];
    const uint32_t sb = smem_u32(smem);
    const int tid = threadIdx.x;
    const int wid = tid >> 5;
    const int lane = tid & 31;
    const int wm = wid >> 1;
    const int wn = wid & 1;
    const int m0 = blockIdx.y * 128;
    const int n0 = blockIdx.x * 128;        // [0, 3072)
    const int lr = lane >> 2;
    const int lc = lane & 3;

    float acc[2][8][4];
#pragma unroll
    for (int mt = 0; mt < 2; ++mt)
#pragma unroll
        for (int nt = 0; nt < 8; ++nt)
#pragma unroll
            for (int i = 0; i < 4; ++i) acc[mt][nt][i] = 0.0f;

    gemm_mainloop(X, W, sb, m0, n0, tid, wm, wn, acc);

    const int target = blockIdx.x >> 3;         // 0=Q, 1=K, 2=V
    const int b = m0 >> 11;
    const int sq0 = m0 & 2047;
    __half* T = smem;                           // [128][136] halves

    if (target < 2) {
        // ---- stage half(acc + bias) tile; acc registers die here ----
#pragma unroll
        for (int nt = 0; nt < 8; ++nt) {
            int col = wn * 64 + nt * 8 + 2 * lc;    // 0..127
            int ncol = n0 + col;
            float b0 = __ldg(&bias[ncol]);
            float b1 = __ldg(&bias[ncol + 1]);
#pragma unroll
            for (int mt = 0; mt < 2; ++mt) {
                int row = wm * 32 + mt * 16 + lr;
                *(__half2*)&T[row * 136 + col] =
                    __floats2half2_rn(acc[mt][nt][0] + b0, acc[mt][nt][1] + b1);
                *(__half2*)&T[(row + 8) * 136 + col] =
                    __floats2half2_rn(acc[mt][nt][2] + b0, acc[mt][nt][3] + b1);
            }
        }
        __syncthreads();

        // ---- rope (fp32, identical math to former rope2 kernel) ----
        __half* Y = (target == 0) ? Qo : Ko;
        const float qs = (target == 0) ? 0.125f : 1.0f;
#pragma unroll
        for (int t = 0; t < 16; ++t) {
            int idx = tid + t * 256;       // 0..4095
            int row = idx >> 5;            // 0..127
            int u = idx & 31;
            int hsel = u >> 4;             // 0..1
            int i2 = (u & 15) * 2;         // 0,2,..,30
            int colL = hsel * 64 + i2;
            float2 xl = __half22float2(*(__half2*)&T[row * 136 + colL]);
            float2 xh = __half22float2(*(__half2*)&T[row * 136 + colL + 32]);
            int s = sq0 + row;
            float2 c2 = *(const float2*)&cosb[s * HD + i2];
            float2 s2 = *(const float2*)&sinb[s * HD + i2];
            float y0 = (xl.x * c2.x - xh.x * s2.x) * qs;
            float y1 = (xl.y * c2.y - xh.y * s2.y) * qs;
            float z0 = (xh.x * c2.x + xl.x * s2.x) * qs;
            float z1 = (xh.y * c2.y + xl.y * s2.y) * qs;
            int head = ((blockIdx.x & 7) << 1) + hsel;
            size_t base = ((size_t)(b * HH + head) * SS + s) * HD + i2;
            *(__half2*)&Y[base] = __floats2half2_rn(y0, y1);
            *(__half2*)&Y[base + 32] = __floats2half2_rn(z0, z1);
        }
    } else {
        // ---- V: smem transpose -> coalesced [B,H,hd,S] stores ----
#pragma unroll
        for (int nt = 0; nt < 8; ++nt) {
            int col = wn * 64 + nt * 8 + 2 * lc;   // 0..127
            int ncol = n0 + col;
            float b0 = __ldg(&bias[ncol]);
            float b1 = __ldg(&bias[ncol + 1]);
#pragma unroll
            for (int mt = 0; mt < 2; ++mt) {
                int row = wm * 32 + mt * 16 + lr;
                T[col * 136 + row] = __float2half_rn(acc[mt][nt][0] + b0);
                T[(col + 1) * 136 + row] = __float2half_rn(acc[mt][nt][1] + b1);
                T[col * 136 + row + 8] = __float2half_rn(acc[mt][nt][2] + b0);
                T[(col + 1) * 136 + row + 8] = __float2half_rn(acc[mt][nt][3] + b1);
            }
        }
        __syncthreads();

#pragma unroll
        for (int t = 0; t < 8; ++t) {
            int idx = tid + t * 256;
            int drow = idx >> 4;                // 0..127
            int c8 = (idx & 15) * 8;
            int hh = ((blockIdx.x & 7) << 1) + (drow >> 6);
            int dd = drow & 63;
            uint4 v = *(const uint4*)&T[drow * 136 + c8];
            *(uint4*)&Vo[((size_t)(b * HH + hh) * HD + dd) * SS + sq0 + c8] = v;
        }
    }
}

// ===========================================================================
// O-projection GEMM (fp32 output)
// ===========================================================================
__global__ __launch_bounds__(256, 2)
void gemm_o_kernel(const __half* __restrict__ X, const __half* __restrict__ W,
                   const float* __restrict__ bias, float* __restrict__ Y)
{
    extern __shared__ __align__(16) __half smem[];
    const uint32_t sb = smem_u32(smem);
    const int tid = threadIdx.x;
    const int wid = tid >> 5;
    const int lane = tid & 31;
    const int wm = wid >> 1;
    const int wn = wid & 1;
    const int m0 = blockIdx.y * 128;
    const int n0 = blockIdx.x * 128;
    const int lr = lane >> 2;
    const int lc = lane & 3;

    float acc[2][8][4];
#pragma unroll
    for (int mt = 0; mt < 2; ++mt)
#pragma unroll
        for (int nt = 0; nt < 8; ++nt)
#pragma unroll
            for (int i = 0; i < 4; ++i) acc[mt][nt][i] = 0.0f;

    gemm_mainloop(X, W, sb, m0, n0, tid, wm, wn, acc);

#pragma unroll
    for (int nt = 0; nt < 8; ++nt) {
        int ncol = n0 + wn * 64 + nt * 8 + 2 * lc;
        float b0 = __ldg(&bias[ncol]);
        float b1 = __ldg(&bias[ncol + 1]);
#pragma unroll
        for (int mt = 0; mt < 2; ++mt) {
            int m = m0 + wm * 32 + mt * 16 + lr;
            *(float2*)&Y[(size_t)m * DD + ncol] =
                make_float2(acc[mt][nt][0] + b0, acc[mt][nt][1] + b1);
            *(float2*)&Y[(size_t)(m + 8) * DD + ncol] =
                make_float2(acc[mt][nt][2] + b0, acc[mt][nt][3] + b1);
        }
    }
}

// ===========================================================================
// Flash attention via mma.sync fp16 (unchanged from Round 15).
// ===========================================================================
#define FPADH 72
#define H_KS0 0
#define H_VS0 (2 * 64 * FPADH)
#define H_QP  (4 * 64 * FPADH)
#define FLASH_SMEM ((4 * 64 * FPADH + 128 * FPADH) * 2)   // 55296 bytes

__device__ __forceinline__ void flash_load_kv(
    const __half* __restrict__ Kg, const __half* __restrict__ Vtg,
    int tid, uint32_t ks_addr, uint32_t vs_addr)
{
#pragma unroll
    for (int t = 0; t < 2; ++t) {
        int idx = tid + t * 256;
        int row = idx >> 3;
        int c = idx & 7;
        const __half* srcK = Kg + row * HD + c * 8;
        const __half* srcV = Vtg + (size_t)row * SS + c * 8;
        uint32_t dK = ks_addr + (row * FPADH + c * 8) * 2;
        uint32_t dV = vs_addr + (row * FPADH + c * 8) * 2;
        asm volatile("cp.async.cg.shared.global [%0], [%1], 16;" :: "r"(dK), "l"(srcK));
        asm volatile("cp.async.cg.shared.global [%0], [%1], 16;" :: "r"(dV), "l"(srcV));
    }
}

__global__ __launch_bounds__(256, 2)
void flash_h_kernel(const __half* __restrict__ Q, const __half* __restrict__ K,
                    const __half* __restrict__ Vt, __half* __restrict__ O)
{
    extern __shared__ __align__(16) __half sm[];
    const uint32_t sb = smem_u32(sm);

    const int tid = threadIdx.x;
    const int w = tid >> 5;
    const int lane = tid & 31;
    const int lr = lane >> 2;
    const int lc = lane & 3;
    const int lt = lane >> 3;       // ldmatrix tile index 0..3
    const int ltr = lane & 7;       // row within tile

    const int qt = (SS / 128 - 1) - blockIdx.x;
    const int h  = blockIdx.y;
    const int b  = blockIdx.z;
    const int bh = b * HH + h;

    const __half* Qg = Q + ((size_t)bh * SS + qt * 128) * HD;
    const __half* Kb = K + (size_t)bh * SS * HD;
    const __half* Vb = Vt + (size_t)bh * HD * SS;

    const uint32_t kv_off =
        (((lt >> 1) * 8 + ltr) * FPADH + (lt & 1) * 8) * 2;
    const uint32_t p_off =
        ((w * 16 + (lt & 1) * 8 + ltr) * FPADH + (lt >> 1) * 8) * 2;
    const uint32_t qp_base = sb + H_QP * 2;

    __half* QP = sm + H_QP;
#pragma unroll
    for (int t = 0; t < 4; ++t) {
        int idx = tid + t * 256;
        int row = idx >> 3;
        int c8 = (idx & 7) * 8;
        *(uint4*)&QP[row * FPADH + c8] = *(const uint4*)(Qg + row * HD + c8);
    }
    __syncthreads();

    uint32_t qa[4][4];
#pragma unroll
    for (int kk = 0; kk < 4; ++kk) {
        LDSM4(qa[kk][0], qa[kk][1], qa[kk][2], qa[kk][3],
              qp_base + p_off + kk * 32);
    }

    float oacc[8][4];
#pragma unroll
    for (int nt = 0; nt < 8; ++nt)
#pragma unroll
        for (int i = 0; i < 4; ++i) oacc[nt][i] = 0.0f;
    float mA = -INFINITY, mB = -INFINITY, lA = 0.0f, lB = 0.0f;

    const int jmax = 2 * qt + 1;

    flash_load_kv(Kb, Vb, tid, sb + H_KS0 * 2, sb + H_VS0 * 2);
    asm volatile("cp.async.commit_group;" ::: "memory");

    __half* Pt = QP;

    for (int j = 0; j <= jmax; ++j) {
        asm volatile("cp.async.wait_group 0;" ::: "memory");
        __syncthreads();

        if (j + 1 <= jmax) {
            int st = (j + 1) & 1;
            flash_load_kv(Kb + (size_t)(j + 1) * 64 * HD,
                          Vb + (size_t)(j + 1) * 64, tid,
                          sb + (H_KS0 + st * 64 * FPADH) * 2,
                          sb + (H_VS0 + st * 64 * FPADH) * 2);
            asm volatile("cp.async.commit_group;" ::: "memory");
        }

        const int st = j & 1;
        const uint32_t ksb = sb + (H_KS0 + st * 64 * FPADH) * 2;
        const uint32_t vsb = sb + (H_VS0 + st * 64 * FPADH) * 2;

        float sacc[8][4];
#pragma unroll
        for (int nt = 0; nt < 8; ++nt)
#pragma unroll
            for (int i = 0; i < 4; ++i) sacc[nt][i] = 0.0f;

#pragma unroll
        for (int kk = 0; kk < 4; ++kk) {
#pragma unroll
            for (int p = 0; p < 4; ++p) {
                uint32_t bf[4];
                LDSM4(bf[0], bf[1], bf[2], bf[3],
                      ksb + kv_off + (p * 16 * FPADH + kk * 16) * 2);
                mma_f16(sacc[2 * p], qa[kk], bf);
                mma_f16(sacc[2 * p + 1], qa[kk], bf + 2);
            }
        }

        if (j >= 2 * qt) {
            int rowA = qt * 128 + w * 16 + lr;
            int rowB = rowA + 8;
#pragma unroll
            for (int nt = 0; nt < 8; ++nt) {
                int c0 = j * 64 + nt * 8 + 2 * lc;
                int c1 = c0 + 1;
                if (c0 > rowA) sacc[nt][0] = -1.0e30f;
                if (c1 > rowA) sacc[nt][1] = -1.0e30f;
                if (c0 > rowB) sacc[nt][2] = -1.0e30f;
                if (c1 > rowB) sacc[nt][3] = -1.0e30f;
            }
        }

        float mxA = -INFINITY, mxB = -INFINITY;
#pragma unroll
        for (int nt = 0; nt < 8; ++nt) {
            mxA = fmaxf(mxA, fmaxf(sacc[nt][0], sacc[nt][1]));
            mxB = fmaxf(mxB, fmaxf(sacc[nt][2], sacc[nt][3]));
        }
        mxA = fmaxf(mxA, __shfl_xor_sync(0xffffffffu, mxA, 1));
        mxA = fmaxf(mxA, __shfl_xor_sync(0xffffffffu, mxA, 2));
        mxB = fmaxf(mxB, __shfl_xor_sync(0xffffffffu, mxB, 1));
        mxB = fmaxf(mxB, __shfl_xor_sync(0xffffffffu, mxB, 2));

        float mnA = fmaxf(mA, mxA);
        float mnB = fmaxf(mB, mxB);
        float corrA = __expf(mA - mnA);
        float corrB = __expf(mB - mnB);
        mA = mnA; mB = mnB;

        float rsA = 0.0f, rsB = 0.0f;
#pragma unroll
        for (int nt = 0; nt < 8; ++nt) {
            sacc[nt][0] = __expf(sacc[nt][0] - mnA);
            sacc[nt][1] = __expf(sacc[nt][1] - mnA);
            sacc[nt][2] = __expf(sacc[nt][2] - mnB);
            sacc[nt][3] = __expf(sacc[nt][3] - mnB);
            rsA += sacc[nt][0] + sacc[nt][1];
            rsB += sacc[nt][2] + sacc[nt][3];
        }
        rsA += __shfl_xor_sync(0xffffffffu, rsA, 1);
        rsA += __shfl_xor_sync(0xffffffffu, rsA, 2);
        rsB += __shfl_xor_sync(0xffffffffu, rsB, 1);
        rsB += __shfl_xor_sync(0xffffffffu, rsB, 2);
        lA = lA * corrA + rsA;
        lB = lB * corrB + rsB;

#pragma unroll
        for (int nt = 0; nt < 8; ++nt) {
            oacc[nt][0] *= corrA;
            oacc[nt][1] *= corrA;
            oacc[nt][2] *= corrB;
            oacc[nt][3] *= corrB;
        }

        {
            int rA = w * 16 + lr;
#pragma unroll
            for (int nt = 0; nt < 8; ++nt) {
                int c = nt * 8 + 2 * lc;
                *(__half2*)&Pt[rA * FPADH + c] =
                    __floats2half2_rn(sacc[nt][0], sacc[nt][1]);
                *(__half2*)&Pt[(rA + 8) * FPADH + c] =
                    __floats2half2_rn(sacc[nt][2], sacc[nt][3]);
            }
        }
        __syncwarp();

#pragma unroll
        for (int kk = 0; kk < 4; ++kk) {
            uint32_t pa[4];
            LDSM4(pa[0], pa[1], pa[2], pa[3], qp_base + p_off + kk * 32);
#pragma unroll
            for (int p = 0; p < 4; ++p) {
                uint32_t vf[4];
                LDSM4(vf[0], vf[1], vf[2], vf[3],
                      vsb + kv_off + (p * 16 * FPADH + kk * 16) * 2);
                mma_f16(oacc[2 * p], pa, vf);
                mma_f16(oacc[2 * p + 1], pa, vf + 2);
            }
        }
        __syncwarp();
    }

    float invA = 1.0f / lA;
    float invB = 1.0f / lB;
    int rowA = qt * 128 + w * 16 + lr;
    __half* Og = O + ((size_t)b * SS) * DD + h * HD;
#pragma unroll
    for (int nt = 0; nt < 8; ++nt) {
        int d = nt * 8 + 2 * lc;
        *(__half2*)&Og[(size_t)rowA * DD + d] =
            __floats2half2_rn(oacc[nt][0] * invA, oacc[nt][1] * invA);
        *(__half2*)&Og[(size_t)(rowA + 8) * DD + d] =
            __floats2half2_rn(oacc[nt][2] * invB, oacc[nt][3] * invB);
    }
}

// ---------------------------------------------------------------------------
// kernel_launch
// Input order: x, mask, rope_cos, rope_sin, Wq, bq, Wk, bk, Wv, bv, Wo, bo
// ---------------------------------------------------------------------------
extern "C" void kernel_launch(void* const* d_in, const int* in_sizes, int n_in,
                              void* d_out, int out_size)
{
    (void)in_sizes; (void)n_in; (void)out_size;

    const float* x    = (const float*)d_in[0];
    const float* cosb = (const float*)d_in[2];
    const float* sinb = (const float*)d_in[3];
    const float* Wq = (const float*)d_in[4];
    const float* bq = (const float*)d_in[5];
    const float* Wk = (const float*)d_in[6];
    const float* bk = (const float*)d_in[7];
    const float* Wv = (const float*)d_in[8];
    const float* bv = (const float*)d_in[9];
    const float* Wo = (const float*)d_in[10];
    const float* bo = (const float*)d_in[11];
    float* out = (float*)d_out;

    __half *Qh, *Kh, *Vt, *Ch, *Xh, *Wh;
    float* biasp;
    cudaGetSymbolAddress((void**)&Qh, g_Qh);
    cudaGetSymbolAddress((void**)&Kh, g_Kh);
    cudaGetSymbolAddress((void**)&Vt, g_Vt);
    cudaGetSymbolAddress((void**)&Ch, g_ctx);
    cudaGetSymbolAddress((void**)&Xh, g_Xh);
    cudaGetSymbolAddress((void**)&Wh, g_Wh);
    cudaGetSymbolAddress((void**)&biasp, g_bias);

    cudaFuncSetAttribute(gemm_qkv_kernel,
                         cudaFuncAttributeMaxDynamicSharedMemorySize, GEMM_SMEM);
    cudaFuncSetAttribute(gemm_o_kernel,
                         cudaFuncAttributeMaxDynamicSharedMemorySize, GEMM_SMEM);
    cudaFuncSetAttribute(flash_h_kernel,
                         cudaFuncAttributeMaxDynamicSharedMemorySize, FLASH_SMEM);

    // --- convert all fp32 inputs to fp16 + pack bias (one launch) ---
    cvt_all_kernel<<<(CVT_TOTAL + 255) / 256, 256>>>(
        x, Wq, Wk, Wv, Wo, bq, bk, bv, Xh, Wh, biasp);

    // --- fused QKV projection with rope in epilogue ---
    gemm_qkv_kernel<<<dim3(24, 64), 256, GEMM_SMEM>>>(
        Xh, Wh, biasp, cosb, sinb, Qh, Kh, Vt);

    // --- attention ---
    flash_h_kernel<<<dim3(SS / 128, HH, BB), 256, FLASH_SMEM>>>(Qh, Kh, Vt, Ch);

    // --- output projection ---
    gemm_o_kernel<<<dim3(8, 64), 256, GEMM_SMEM>>>(Ch, Wh + 3 * DD * DD, bo, out);
}

// round 17
// speedup vs baseline: 1.6645x; 1.0522x over previous
#include <cuda_runtime.h>
#include <cuda_fp16.h>
#include <math.h>
#include <stdint.h>

// Problem constants
#define BB 4
#define HH 16
#define SS 2048
#define DD 1024
#define HD 64
#define MROWS (BB * SS)   // 8192

// ---------------------------------------------------------------------------
// Scratch (no allocations allowed -> __device__ globals)
// ---------------------------------------------------------------------------
__device__ __half g_Qh[BB * HH * SS * HD];
__device__ __half g_Kh[BB * HH * SS * HD];
__device__ __half g_Vt[BB * HH * HD * SS];   // [b,h,d,s] transposed
__device__ __half g_ctx[BB * SS * DD];
__device__ __half g_Xh[MROWS * DD];
__device__ __half g_Wh[4 * DD * DD];         // Wq|Wk|Wv|Wo packed
__device__ float  g_bias[3 * DD];            // bq|bk|bv packed

// ---------------------------------------------------------------------------
// helpers
// ---------------------------------------------------------------------------
__device__ __forceinline__ uint32_t smem_u32(const void* p) {
    uint32_t a;
    asm("{ .reg .u64 t; cvta.to.shared.u64 t, %1; cvt.u32.u64 %0, t; }"
        : "=r"(a) : "l"(p));
    return a;
}

// mma.sync m16n8k16 fp16 in, fp32 accumulate (in place on d)
__device__ __forceinline__ void mma_f16(float d[4], const uint32_t a[4],
                                        const uint32_t b[2]) {
    asm volatile(
        "mma.sync.aligned.m16n8k16.row.col.f32.f16.f16.f32 "
        "{%0,%1,%2,%3}, {%4,%5,%6,%7}, {%8,%9}, {%0,%1,%2,%3};"
        : "+f"(d[0]), "+f"(d[1]), "+f"(d[2]), "+f"(d[3])
        : "r"(a[0]), "r"(a[1]), "r"(a[2]), "r"(a[3]), "r"(b[0]), "r"(b[1]));
}

#define LDSM4(R0, R1, R2, R3, addr) \
    asm volatile("ldmatrix.sync.aligned.m8n8.x4.shared.b16 {%0,%1,%2,%3}, [%4];" \
                 : "=r"(R0), "=r"(R1), "=r"(R2), "=r"(R3) : "r"(addr))

// ---------------------------------------------------------------------------
// Single conversion kernel (x, 4 weights, packed bias) in one launch.
// ---------------------------------------------------------------------------
#define XN4 (MROWS * DD / 4)        // 2097152
#define WN4 (DD * DD / 4)           // 262144
#define CVT_TOTAL (XN4 + 4 * WN4 + 3 * DD)

__global__ void cvt_all_kernel(const float* __restrict__ x,
                               const float* __restrict__ Wq,
                               const float* __restrict__ Wk,
                               const float* __restrict__ Wv,
                               const float* __restrict__ Wo,
                               const float* __restrict__ bq,
                               const float* __restrict__ bk,
                               const float* __restrict__ bv,
                               __half* __restrict__ Xh,
                               __half* __restrict__ Wh,
                               float* __restrict__ biasp)
{
    int i = blockIdx.x * blockDim.x + threadIdx.x;
    if (i >= CVT_TOTAL) return;
    if (i >= XN4 + 4 * WN4) {
        int j = i - (XN4 + 4 * WN4);        // < 3072
        float v;
        if (j < 1024) v = bq[j];
        else if (j < 2048) v = bk[j - 1024];
        else v = bv[j - 2048];
        biasp[j] = v;
        return;
    }
    const float* src;
    __half* dst;
    int off;
    if (i < XN4) {
        src = x; dst = Xh; off = i;
    } else {
        int j = i - XN4;
        int w = j >> 18;            // / WN4
        off = j & (WN4 - 1);
        src = (w == 0) ? Wq : (w == 1) ? Wk : (w == 2) ? Wv : Wo;
        dst = Wh + (size_t)w * DD * DD;
    }
    float4 v = ((const float4*)src)[off];
    ((__half2*)dst)[2 * off]     = __floats2half2_rn(v.x, v.y);
    ((__half2*)dst)[2 * off + 1] = __floats2half2_rn(v.z, v.w);
}

// ===========================================================================
// Shared GEMM machinery: CTA tile 128x128, BK=64 halves, 8 warps (4m x 2n),
// warp tile 32x64. 3-stage cp.async ring, single-sync stage rotation.
// Pad-72 rows (144B stride) - conflict-free ldmatrix (proven in flash).
// ===========================================================================
#define GBK 64
#define GPADH 72
#define GSTAGE_BYTES (2 * 128 * GPADH * 2)   // 36864
#define GNSTAGE 3
#define GEMM_SMEM (GNSTAGE * GSTAGE_BYTES)   // 110592

__device__ __forceinline__ void gemm_issue_loads(
    const __half* __restrict__ X, const __half* __restrict__ W,
    int m0, int n0, int tid, uint32_t stage_addr, int k0)
{
    // A: 128 rows x 64 halves (128B = 8 x 16B chunks per row)
#pragma unroll
    for (int t = 0; t < 4; ++t) {
        int idx = tid + t * 256;       // 0..1023
        int row = idx >> 3;
        int c = idx & 7;
        const __half* src = X + (size_t)(m0 + row) * 1024 + k0 + c * 8;
        uint32_t dst = stage_addr + row * (GPADH * 2) + c * 16;
        asm volatile("cp.async.cg.shared.global [%0], [%1], 16;"
                     :: "r"(dst), "l"(src));
    }
#pragma unroll
    for (int t = 0; t < 4; ++t) {
        int idx = tid + t * 256;
        int row = idx >> 3;
        int c = idx & 7;
        const __half* src = W + (size_t)(n0 + row) * 1024 + k0 + c * 8;
        uint32_t dst = stage_addr + 128 * (GPADH * 2) + row * (GPADH * 2) + c * 16;
        asm volatile("cp.async.cg.shared.global [%0], [%1], 16;"
                     :: "r"(dst), "l"(src));
    }
}

__device__ __forceinline__ void gemm_mainloop(
    const __half* __restrict__ X, const __half* __restrict__ W,
    uint32_t sb, int m0, int n0, int tid,
    int wm, int wn, float acc[2][8][4])
{
    const int lane = tid & 31;
    const int lt = lane >> 3;       // tile index 0..3
    const int ltr = lane & 7;       // row within tile

    const uint32_t a_off =
        ((wm * 32 + (lt & 1) * 8 + ltr) * GPADH + (lt >> 1) * 8) * 2;
    const uint32_t b_off = 128 * (GPADH * 2) +
        ((wn * 64 + (lt >> 1) * 8 + ltr) * GPADH + (lt & 1) * 8) * 2;

    gemm_issue_loads(X, W, m0, n0, tid, sb + 0 * GSTAGE_BYTES, 0);
    asm volatile("cp.async.commit_group;" ::: "memory");
    gemm_issue_loads(X, W, m0, n0, tid, sb + 1 * GSTAGE_BYTES, GBK);
    asm volatile("cp.async.commit_group;" ::: "memory");

    const int NK = 1024 / GBK;   // 16
    for (int s = 0; s < NK; ++s) {
        // stage s resident: allow 1 younger pending group while more remain
        if (s <= NK - 2)
            asm volatile("cp.async.wait_group 1;" ::: "memory");
        else
            asm volatile("cp.async.wait_group 0;" ::: "memory");
        __syncthreads();   // also proves all threads completed compute of s-1

        int t = s + 2;
        if (t < NK) {
            gemm_issue_loads(X, W, m0, n0, tid,
                             sb + (t % GNSTAGE) * GSTAGE_BYTES, t * GBK);
            asm volatile("cp.async.commit_group;" ::: "memory");
        }

        const uint32_t st_b = sb + (s % GNSTAGE) * GSTAGE_BYTES;

#pragma unroll
        for (int kk = 0; kk < 4; ++kk) {     // 4 x k16
            uint32_t af[2][4];
#pragma unroll
            for (int mt = 0; mt < 2; ++mt) {
                LDSM4(af[mt][0], af[mt][1], af[mt][2], af[mt][3],
                      st_b + a_off + (mt * 16 * GPADH + kk * 16) * 2);
            }
            uint32_t bf[8][2];
#pragma unroll
            for (int p = 0; p < 4; ++p) {
                LDSM4(bf[2 * p][0], bf[2 * p][1], bf[2 * p + 1][0], bf[2 * p + 1][1],
                      st_b + b_off + (p * 16 * GPADH + kk * 16) * 2);
            }
#pragma unroll
            for (int mt = 0; mt < 2; ++mt)
#pragma unroll
                for (int nt = 0; nt < 8; ++nt)
                    mma_f16(acc[mt][nt], af[mt], bf[nt]);
        }
    }
    __syncthreads();   // epilogue may reuse smem
}

// ===========================================================================
// Fused QKV GEMM: N=3072 over packed Wq|Wk|Wv.
// Q/K epilogue: stage half(acc+bias) in smem (acc dies), reload + fp32 rope,
// store [B,H,S,hd]. V epilogue: smem transpose -> coalesced [B,H,hd,S].
// ===========================================================================
__global__ __launch_bounds__(256, 2)
void gemm_qkv_kernel(const __half* __restrict__ X, const __half* __restrict__ W,
                     const float* __restrict__ bias,
                     const float* __restrict__ cosb,
                     const float* __restrict__ sinb,
                     __half* __restrict__ Qo, __half* __restrict__ Ko,
                     __half* __restrict__ Vo)
{
    extern __shared__ __align__(16) __half smem[];
    const uint32_t sb = smem_u32(smem);
    const int tid = threadIdx.x;
    const int wid = tid >> 5;
    const int lane = tid & 31;
    const int wm = wid >> 1;
    const int wn = wid & 1;
    const int m0 = blockIdx.y * 128;
    const int n0 = blockIdx.x * 128;        // [0, 3072)
    const int lr = lane >> 2;
    const int lc = lane & 3;

    float acc[2][8][4];
#pragma unroll
    for (int mt = 0; mt < 2; ++mt)
#pragma unroll
        for (int nt = 0; nt < 8; ++nt)
#pragma unroll
            for (int i = 0; i < 4; ++i) acc[mt][nt][i] = 0.0f;

    gemm_mainloop(X, W, sb, m0, n0, tid, wm, wn, acc);

    const int target = blockIdx.x >> 3;         // 0=Q, 1=K, 2=V
    const int b = m0 >> 11;
    const int sq0 = m0 & 2047;
    __half* T = smem;                           // [128][136] halves

    if (target < 2) {
        // ---- stage half(acc + bias) tile; acc registers die here ----
#pragma unroll
        for (int nt = 0; nt < 8; ++nt) {
            int col = wn * 64 + nt * 8 + 2 * lc;    // 0..127
            int ncol = n0 + col;
            float b0 = __ldg(&bias[ncol]);
            float b1 = __ldg(&bias[ncol + 1]);
#pragma unroll
            for (int mt = 0; mt < 2; ++mt) {
                int row = wm * 32 + mt * 16 + lr;
                *(__half2*)&T[row * 136 + col] =
                    __floats2half2_rn(acc[mt][nt][0] + b0, acc[mt][nt][1] + b1);
                *(__half2*)&T[(row + 8) * 136 + col] =
                    __floats2half2_rn(acc[mt][nt][2] + b0, acc[mt][nt][3] + b1);
            }
        }
        __syncthreads();

        // ---- rope (fp32, identical math to former rope2 kernel) ----
        __half* Y = (target == 0) ? Qo : Ko;
        const float qs = (target == 0) ? 0.125f : 1.0f;
#pragma unroll
        for (int t = 0; t < 16; ++t) {
            int idx = tid + t * 256;       // 0..4095
            int row = idx >> 5;            // 0..127
            int u = idx & 31;
            int hsel = u >> 4;             // 0..1
            int i2 = (u & 15) * 2;         // 0,2,..,30
            int colL = hsel * 64 + i2;
            float2 xl = __half22float2(*(__half2*)&T[row * 136 + colL]);
            float2 xh = __half22float2(*(__half2*)&T[row * 136 + colL + 32]);
            int s = sq0 + row;
            float2 c2 = *(const float2*)&cosb[s * HD + i2];
            float2 s2 = *(const float2*)&sinb[s * HD + i2];
            float y0 = (xl.x * c2.x - xh.x * s2.x) * qs;
            float y1 = (xl.y * c2.y - xh.y * s2.y) * qs;
            float z0 = (xh.x * c2.x + xl.x * s2.x) * qs;
            float z1 = (xh.y * c2.y + xl.y * s2.y) * qs;
            int head = ((blockIdx.x & 7) << 1) + hsel;
            size_t base = ((size_t)(b * HH + head) * SS + s) * HD + i2;
            *(__half2*)&Y[base] = __floats2half2_rn(y0, y1);
            *(__half2*)&Y[base + 32] = __floats2half2_rn(z0, z1);
        }
    } else {
        // ---- V: smem transpose -> coalesced [B,H,hd,S] stores ----
#pragma unroll
        for (int nt = 0; nt < 8; ++nt) {
            int col = wn * 64 + nt * 8 + 2 * lc;   // 0..127
            int ncol = n0 + col;
            float b0 = __ldg(&bias[ncol]);
            float b1 = __ldg(&bias[ncol + 1]);
#pragma unroll
            for (int mt = 0; mt < 2; ++mt) {
                int row = wm * 32 + mt * 16 + lr;
                T[col * 136 + row] = __float2half_rn(acc[mt][nt][0] + b0);
                T[(col + 1) * 136 + row] = __float2half_rn(acc[mt][nt][1] + b1);
                T[col * 136 + row + 8] = __float2half_rn(acc[mt][nt][2] + b0);
                T[(col + 1) * 136 + row + 8] = __float2half_rn(acc[mt][nt][3] + b1);
            }
        }
        __syncthreads();

#pragma unroll
        for (int t = 0; t < 8; ++t) {
            int idx = tid + t * 256;
            int drow = idx >> 4;                // 0..127
            int c8 = (idx & 15) * 8;
            int hh = ((blockIdx.x & 7) << 1) + (drow >> 6);
            int dd = drow & 63;
            uint4 v = *(const uint4*)&T[drow * 136 + c8];
            *(uint4*)&Vo[((size_t)(b * HH + hh) * HD + dd) * SS + sq0 + c8] = v;
        }
    }
}

// ===========================================================================
// O-projection GEMM (fp32 output)
// ===========================================================================
__global__ __launch_bounds__(256, 2)
void gemm_o_kernel(const __half* __restrict__ X, const __half* __restrict__ W,
                   const float* __restrict__ bias, float* __restrict__ Y)
{
    extern __shared__ __align__(16) __half smem[];
    const uint32_t sb = smem_u32(smem);
    const int tid = threadIdx.x;
    const int wid = tid >> 5;
    const int lane = tid & 31;
    const int wm = wid >> 1;
    const int wn = wid & 1;
    const int m0 = blockIdx.y * 128;
    const int n0 = blockIdx.x * 128;
    const int lr = lane >> 2;
    const int lc = lane & 3;

    float acc[2][8][4];
#pragma unroll
    for (int mt = 0; mt < 2; ++mt)
#pragma unroll
        for (int nt = 0; nt < 8; ++nt)
#pragma unroll
            for (int i = 0; i < 4; ++i) acc[mt][nt][i] = 0.0f;

    gemm_mainloop(X, W, sb, m0, n0, tid, wm, wn, acc);

#pragma unroll
    for (int nt = 0; nt < 8; ++nt) {
        int ncol = n0 + wn * 64 + nt * 8 + 2 * lc;
        float b0 = __ldg(&bias[ncol]);
        float b1 = __ldg(&bias[ncol + 1]);
#pragma unroll
        for (int mt = 0; mt < 2; ++mt) {
            int m = m0 + wm * 32 + mt * 16 + lr;
            *(float2*)&Y[(size_t)m * DD + ncol] =
                make_float2(acc[mt][nt][0] + b0, acc[mt][nt][1] + b1);
            *(float2*)&Y[(size_t)(m + 8) * DD + ncol] =
                make_float2(acc[mt][nt][2] + b0, acc[mt][nt][3] + b1);
        }
    }
}

// ===========================================================================
// Flash attention via mma.sync fp16 (unchanged from Round 16).
// ===========================================================================
#define FPADH 72
#define H_KS0 0
#define H_VS0 (2 * 64 * FPADH)
#define H_QP  (4 * 64 * FPADH)
#define FLASH_SMEM ((4 * 64 * FPADH + 128 * FPADH) * 2)   // 55296 bytes

__device__ __forceinline__ void flash_load_kv(
    const __half* __restrict__ Kg, const __half* __restrict__ Vtg,
    int tid, uint32_t ks_addr, uint32_t vs_addr)
{
#pragma unroll
    for (int t = 0; t < 2; ++t) {
        int idx = tid + t * 256;
        int row = idx >> 3;
        int c = idx & 7;
        const __half* srcK = Kg + row * HD + c * 8;
        const __half* srcV = Vtg + (size_t)row * SS + c * 8;
        uint32_t dK = ks_addr + (row * FPADH + c * 8) * 2;
        uint32_t dV = vs_addr + (row * FPADH + c * 8) * 2;
        asm volatile("cp.async.cg.shared.global [%0], [%1], 16;" :: "r"(dK), "l"(srcK));
        asm volatile("cp.async.cg.shared.global [%0], [%1], 16;" :: "r"(dV), "l"(srcV));
    }
}

__global__ __launch_bounds__(256, 2)
void flash_h_kernel(const __half* __restrict__ Q, const __half* __restrict__ K,
                    const __half* __restrict__ Vt, __half* __restrict__ O)
{
    extern __shared__ __align__(16) __half sm[];
    const uint32_t sb = smem_u32(sm);

    const int tid = threadIdx.x;
    const int w = tid >> 5;
    const int lane = tid & 31;
    const int lr = lane >> 2;
    const int lc = lane & 3;
    const int lt = lane >> 3;       // ldmatrix tile index 0..3
    const int ltr = lane & 7;       // row within tile

    const int qt = (SS / 128 - 1) - blockIdx.x;
    const int h  = blockIdx.y;
    const int b  = blockIdx.z;
    const int bh = b * HH + h;

    const __half* Qg = Q + ((size_t)bh * SS + qt * 128) * HD;
    const __half* Kb = K + (size_t)bh * SS * HD;
    const __half* Vb = Vt + (size_t)bh * HD * SS;

    const uint32_t kv_off =
        (((lt >> 1) * 8 + ltr) * FPADH + (lt & 1) * 8) * 2;
    const uint32_t p_off =
        ((w * 16 + (lt & 1) * 8 + ltr) * FPADH + (lt >> 1) * 8) * 2;
    const uint32_t qp_base = sb + H_QP * 2;

    __half* QP = sm + H_QP;
#pragma unroll
    for (int t = 0; t < 4; ++t) {
        int idx = tid + t * 256;
        int row = idx >> 3;
        int c8 = (idx & 7) * 8;
        *(uint4*)&QP[row * FPADH + c8] = *(const uint4*)(Qg + row * HD + c8);
    }
    __syncthreads();

    uint32_t qa[4][4];
#pragma unroll
    for (int kk = 0; kk < 4; ++kk) {
        LDSM4(qa[kk][0], qa[kk][1], qa[kk][2], qa[kk][3],
              qp_base + p_off + kk * 32);
    }

    float oacc[8][4];
#pragma unroll
    for (int nt = 0; nt < 8; ++nt)
#pragma unroll
        for (int i = 0; i < 4; ++i) oacc[nt][i] = 0.0f;
    float mA = -INFINITY, mB = -INFINITY, lA = 0.0f, lB = 0.0f;

    const int jmax = 2 * qt + 1;

    flash_load_kv(Kb, Vb, tid, sb + H_KS0 * 2, sb + H_VS0 * 2);
    asm volatile("cp.async.commit_group;" ::: "memory");

    __half* Pt = QP;

    for (int j = 0; j <= jmax; ++j) {
        asm volatile("cp.async.wait_group 0;" ::: "memory");
        __syncthreads();

        if (j + 1 <= jmax) {
            int st = (j + 1) & 1;
            flash_load_kv(Kb + (size_t)(j + 1) * 64 * HD,
                          Vb + (size_t)(j + 1) * 64, tid,
                          sb + (H_KS0 + st * 64 * FPADH) * 2,
                          sb + (H_VS0 + st * 64 * FPADH) * 2);
            asm volatile("cp.async.commit_group;" ::: "memory");
        }

        const int st = j & 1;
        const uint32_t ksb = sb + (H_KS0 + st * 64 * FPADH) * 2;
        const uint32_t vsb = sb + (H_VS0 + st * 64 * FPADH) * 2;

        float sacc[8][4];
#pragma unroll
        for (int nt = 0; nt < 8; ++nt)
#pragma unroll
            for (int i = 0; i < 4; ++i) sacc[nt][i] = 0.0f;

#pragma unroll
        for (int kk = 0; kk < 4; ++kk) {
#pragma unroll
            for (int p = 0; p < 4; ++p) {
                uint32_t bf[4];
                LDSM4(bf[0], bf[1], bf[2], bf[3],
                      ksb + kv_off + (p * 16 * FPADH + kk * 16) * 2);
                mma_f16(sacc[2 * p], qa[kk], bf);
                mma_f16(sacc[2 * p + 1], qa[kk], bf + 2);
            }
        }

        if (j >= 2 * qt) {
            int rowA = qt * 128 + w * 16 + lr;
            int rowB = rowA + 8;
#pragma unroll
            for (int nt = 0; nt < 8; ++nt) {
                int c0 = j * 64 + nt * 8 + 2 * lc;
                int c1 = c0 + 1;
                if (c0 > rowA) sacc[nt][0] = -1.0e30f;
                if (c1 > rowA) sacc[nt][1] = -1.0e30f;
                if (c0 > rowB) sacc[nt][2] = -1.0e30f;
                if (c1 > rowB) sacc[nt][3] = -1.0e30f;
            }
        }

        float mxA = -INFINITY, mxB = -INFINITY;
#pragma unroll
        for (int nt = 0; nt < 8; ++nt) {
            mxA = fmaxf(mxA, fmaxf(sacc[nt][0], sacc[nt][1]));
            mxB = fmaxf(mxB, fmaxf(sacc[nt][2], sacc[nt][3]));
        }
        mxA = fmaxf(mxA, __shfl_xor_sync(0xffffffffu, mxA, 1));
        mxA = fmaxf(mxA, __shfl_xor_sync(0xffffffffu, mxA, 2));
        mxB = fmaxf(mxB, __shfl_xor_sync(0xffffffffu, mxB, 1));
        mxB = fmaxf(mxB, __shfl_xor_sync(0xffffffffu, mxB, 2));

        float mnA = fmaxf(mA, mxA);
        float mnB = fmaxf(mB, mxB);
        float corrA = __expf(mA - mnA);
        float corrB = __expf(mB - mnB);
        mA = mnA; mB = mnB;

        float rsA = 0.0f, rsB = 0.0f;
#pragma unroll
        for (int nt = 0; nt < 8; ++nt) {
            sacc[nt][0] = __expf(sacc[nt][0] - mnA);
            sacc[nt][1] = __expf(sacc[nt][1] - mnA);
            sacc[nt][2] = __expf(sacc[nt][2] - mnB);
            sacc[nt][3] = __expf(sacc[nt][3] - mnB);
            rsA += sacc[nt][0] + sacc[nt][1];
            rsB += sacc[nt][2] + sacc[nt][3];
        }
        rsA += __shfl_xor_sync(0xffffffffu, rsA, 1);
        rsA += __shfl_xor_sync(0xffffffffu, rsA, 2);
        rsB += __shfl_xor_sync(0xffffffffu, rsB, 1);
        rsB += __shfl_xor_sync(0xffffffffu, rsB, 2);
        lA = lA * corrA + rsA;
        lB = lB * corrB + rsB;

#pragma unroll
        for (int nt = 0; nt < 8; ++nt) {
            oacc[nt][0] *= corrA;
            oacc[nt][1] *= corrA;
            oacc[nt][2] *= corrB;
            oacc[nt][3] *= corrB;
        }

        {
            int rA = w * 16 + lr;
#pragma unroll
            for (int nt = 0; nt < 8; ++nt) {
                int c = nt * 8 + 2 * lc;
                *(__half2*)&Pt[rA * FPADH + c] =
                    __floats2half2_rn(sacc[nt][0], sacc[nt][1]);
                *(__half2*)&Pt[(rA + 8) * FPADH + c] =
                    __floats2half2_rn(sacc[nt][2], sacc[nt][3]);
            }
        }
        __syncwarp();

#pragma unroll
        for (int kk = 0; kk < 4; ++kk) {
            uint32_t pa[4];
            LDSM4(pa[0], pa[1], pa[2], pa[3], qp_base + p_off + kk * 32);
#pragma unroll
            for (int p = 0; p < 4; ++p) {
                uint32_t vf[4];
                LDSM4(vf[0], vf[1], vf[2], vf[3],
                      vsb + kv_off + (p * 16 * FPADH + kk * 16) * 2);
                mma_f16(oacc[2 * p], pa, vf);
                mma_f16(oacc[2 * p + 1], pa, vf + 2);
            }
        }
        __syncwarp();
    }

    float invA = 1.0f / lA;
    float invB = 1.0f / lB;
    int rowA = qt * 128 + w * 16 + lr;
    __half* Og = O + ((size_t)b * SS) * DD + h * HD;
#pragma unroll
    for (int nt = 0; nt < 8; ++nt) {
        int d = nt * 8 + 2 * lc;
        *(__half2*)&Og[(size_t)rowA * DD + d] =
            __floats2half2_rn(oacc[nt][0] * invA, oacc[nt][1] * invA);
        *(__half2*)&Og[(size_t)(rowA + 8) * DD + d] =
            __floats2half2_rn(oacc[nt][2] * invB, oacc[nt][3] * invB);
    }
}

// ---------------------------------------------------------------------------
// kernel_launch
// Input order: x, mask, rope_cos, rope_sin, Wq, bq, Wk, bk, Wv, bv, Wo, bo
// ---------------------------------------------------------------------------
extern "C" void kernel_launch(void* const* d_in, const int* in_sizes, int n_in,
                              void* d_out, int out_size)
{
    (void)in_sizes; (void)n_in; (void)out_size;

    const float* x    = (const float*)d_in[0];
    const float* cosb = (const float*)d_in[2];
    const float* sinb = (const float*)d_in[3];
    const float* Wq = (const float*)d_in[4];
    const float* bq = (const float*)d_in[5];
    const float* Wk = (const float*)d_in[6];
    const float* bk = (const float*)d_in[7];
    const float* Wv = (const float*)d_in[8];
    const float* bv = (const float*)d_in[9];
    const float* Wo = (const float*)d_in[10];
    const float* bo = (const float*)d_in[11];
    float* out = (float*)d_out;

    __half *Qh, *Kh, *Vt, *Ch, *Xh, *Wh;
    float* biasp;
    cudaGetSymbolAddress((void**)&Qh, g_Qh);
    cudaGetSymbolAddress((void**)&Kh, g_Kh);
    cudaGetSymbolAddress((void**)&Vt, g_Vt);
    cudaGetSymbolAddress((void**)&Ch, g_ctx);
    cudaGetSymbolAddress((void**)&Xh, g_Xh);
    cudaGetSymbolAddress((void**)&Wh, g_Wh);
    cudaGetSymbolAddress((void**)&biasp, g_bias);

    cudaFuncSetAttribute(gemm_qkv_kernel,
                         cudaFuncAttributeMaxDynamicSharedMemorySize, GEMM_SMEM);
    cudaFuncSetAttribute(gemm_o_kernel,
                         cudaFuncAttributeMaxDynamicSharedMemorySize, GEMM_SMEM);
    cudaFuncSetAttribute(flash_h_kernel,
                         cudaFuncAttributeMaxDynamicSharedMemorySize, FLASH_SMEM);

    // --- convert all fp32 inputs to fp16 + pack bias (one launch) ---
    cvt_all_kernel<<<(CVT_TOTAL + 255) / 256, 256>>>(
        x, Wq, Wk, Wv, Wo, bq, bk, bv, Xh, Wh, biasp);

    // --- fused QKV projection with rope in epilogue ---
    gemm_qkv_kernel<<<dim3(24, 64), 256, GEMM_SMEM>>>(
        Xh, Wh, biasp, cosb, sinb, Qh, Kh, Vt);

    // --- attention ---
    flash_h_kernel<<<dim3(SS / 128, HH, BB), 256, FLASH_SMEM>>>(Qh, Kh, Vt, Ch);

    // --- output projection ---
    gemm_o_kernel<<<dim3(8, 64), 256, GEMM_SMEM>>>(Ch, Wh + 3 * DD * DD, bo, out);
}